// round 6
// baseline (speedup 1.0000x reference)
#include <cuda_runtime.h>
#include <math.h>

#define FULL 0xffffffffu
typedef unsigned long long ull;

static __device__ __forceinline__ float softplusf(float x) {
    return fmaxf(x, 0.f) + log1pf(expf(-fabsf(x)));
}
static __device__ __forceinline__ float sigmf(float x) {
    return __fdividef(1.f, 1.f + __expf(-x));
}
// fast tanh: 1 - 2/(e^{2x}+1); inf-safe at both ends, rel err ~1e-7
static __device__ __forceinline__ float tanh_fast(float x) {
    const float e = __expf(2.f * x);
    return 1.f - __fdividef(2.f, e + 1.f);
}
__host__ __device__ constexpr int TRI(int r, int c) { return r * (r + 1) / 2 + c; }

static __device__ __forceinline__ ull fma2(ull a, ull b, ull c) {
    ull d;
    asm("fma.rn.f32x2 %0, %1, %2, %3;" : "=l"(d) : "l"(a), "l"(b), "l"(c));
    return d;
}
static __device__ __forceinline__ float sum2(ull v) {
    unsigned l, h;
    asm("mov.b64 {%0, %1}, %2;" : "=r"(l), "=r"(h) : "l"(v));
    return __uint_as_float(l) + __uint_as_float(h);
}

// =====================================================================
// Kernel 1: mass + Coriolis. 768 thr (24 warps, 3 groups of 8).
// Virtual element ve = 8*e + v  (e = real element, v = 0:primal, 1-7:tangents).
// Tile = 12 real elements = 96 virtual. lane = ve within group.
// =====================================================================
#define MW1   0        // [d][128] d<7
#define MB1   896
#define MW2P  1024     // [kp][i*2+p]  64*256
#define MB2   17408
#define MW3P  17536    // [kp][i*2+p]  64*56
#define MB3   21120
#define MXIN  21152    // [12][24]: q 0-6, dq 8-14, ddq 16-22
#define MH1   21440    // [96][130]
#define MH2   33920    // [96][130]
#define MA3   46400    // [96][30]
#define M_TOT 49280

__global__ __launch_bounds__(768, 1) void k_mass(
    const float* __restrict__ q, const float* __restrict__ dq, const float* __restrict__ ddq,
    const float* __restrict__ mW1, const float* __restrict__ mb1,
    const float* __restrict__ mW2, const float* __restrict__ mb2,
    const float* __restrict__ mW3, const float* __restrict__ mb3,
    float* __restrict__ out, int batch)
{
    extern __shared__ float sm[];
    const int tid = threadIdx.x;
    for (int i = tid; i < 896; i += 768) sm[MW1 + i] = mW1[i];
    for (int i = tid; i < 128; i += 768) { sm[MB1 + i] = mb1[i]; sm[MB2 + i] = mb2[i]; }
    for (int idx = tid; idx < 16384; idx += 768) {
        const int kp = idx >> 8, r = idx & 255;
        sm[MW2P + idx] = mW2[(2 * kp + (r & 1)) * 128 + (r >> 1)];
    }
    for (int idx = tid; idx < 3584; idx += 768) {
        const int kp = idx / 56, r = idx % 56;
        sm[MW3P + idx] = mW3[(2 * kp + (r & 1)) * 28 + (r >> 1)];
    }
    for (int i = tid; i < 32; i += 768) sm[MB3 + i] = (i < 28) ? mb3[i] : 0.f;
    __syncthreads();

    const int lane = tid & 31;
    const int warp = tid >> 5;          // 0..23
    const int grp  = warp >> 3;         // 0..2
    const int w    = warp & 7;          // output-slice within group
    const int ve   = grp * 32 + lane;   // virtual element within tile (0..95)
    const bool isv0 = (lane & 7) == 0;

    const int ntiles = (batch + 11) / 12;
    for (int tile = blockIdx.x; tile < ntiles; tile += gridDim.x) {
        const int b0 = tile * 12;

        // ---- stage inputs ----
        for (int idx = tid; idx < 288; idx += 768) {
            const int e = idx / 24, s = idx % 24;
            const int b = b0 + e;
            float v = 0.f;
            if (b < batch) {
                if (s < 7) v = q[b * 7 + s];
                else if (s >= 8 && s < 15) v = dq[b * 7 + s - 8];
                else if (s >= 16 && s < 23) v = ddq[b * 7 + s - 16];
            }
            sm[MXIN + idx] = v;
        }
        __syncthreads();

        // ---- layer 1 + tangent seed: 1536 (e,i) pairs, 2 per thread ----
#pragma unroll
        for (int pp = 0; pp < 2; pp++) {
            const int p = tid + pp * 768;
            const int e = p >> 7, i = p & 127;
            float wv[7];
            float z = sm[MB1 + i];
#pragma unroll
            for (int d = 0; d < 7; d++) {
                wv[d] = sm[MW1 + d * 128 + i];
                z = fmaf(sm[MXIN + e * 24 + d], wv[d], z);
            }
            const float h = tanh_fast(z);
            const float g = 1.f - h * h;
            float* hrow = &sm[MH1 + (8 * e) * 130 + i];
            hrow[0] = h;
#pragma unroll
            for (int v = 0; v < 7; v++) hrow[(v + 1) * 130] = g * wv[v];
        }
        __syncthreads();

        // ---- layer 2: warp owns outputs [16w,16w+16) for its 32 ve ----
        {
            ull acc[16];
#pragma unroll
            for (int ii = 0; ii < 16; ii++) acc[ii] = 0ull;
            const float* xrow = &sm[MH1 + ve * 130];
            const float* wbase = &sm[MW2P + w * 32];
#pragma unroll 2
            for (int kp = 0; kp < 64; kp++) {
                const ull x2 = *(const ull*)(xrow + 2 * kp);
                const float* wr = wbase + kp * 256;
#pragma unroll
                for (int m = 0; m < 8; m++) {
                    const double2 wd = *(const double2*)(wr + 4 * m);
                    acc[2 * m]     = fma2(x2, __double_as_longlong(wd.x), acc[2 * m]);
                    acc[2 * m + 1] = fma2(x2, __double_as_longlong(wd.y), acc[2 * m + 1]);
                }
            }
            float* orow = &sm[MH2 + ve * 130];
#pragma unroll
            for (int ii = 0; ii < 16; ii++) {
                const int i = w * 16 + ii;
                const float z = sum2(acc[ii]);
                const float h = tanh_fast(z + sm[MB2 + i]);
                const float gl = 1.f - h * h;
                const float gsh = __shfl_sync(FULL, gl, lane & 24);
                orow[i] = isv0 ? h : gsh * z;
            }
        }
        __syncthreads();

        // ---- layer 3: warps w<7 per group, 4 outputs each ----
        if (w < 7) {
            ull a4[4] = { 0ull, 0ull, 0ull, 0ull };
            const float* xrow = &sm[MH2 + ve * 130];
#pragma unroll 2
            for (int kp = 0; kp < 64; kp++) {
                const ull x2 = *(const ull*)(xrow + 2 * kp);
                const float* wr = &sm[MW3P + kp * 56 + w * 8];
                const double2 w0 = *(const double2*)(wr);
                const double2 w1 = *(const double2*)(wr + 4);
                a4[0] = fma2(x2, __double_as_longlong(w0.x), a4[0]);
                a4[1] = fma2(x2, __double_as_longlong(w0.y), a4[1]);
                a4[2] = fma2(x2, __double_as_longlong(w1.x), a4[2]);
                a4[3] = fma2(x2, __double_as_longlong(w1.y), a4[3]);
            }
#pragma unroll
            for (int ii = 0; ii < 4; ii++) {
                const int i = w * 4 + ii;
                sm[MA3 + ve * 30 + i] = sum2(a4[ii]) + (isv0 ? sm[MB3 + i] : 0.f);
            }
        }
        __syncthreads();

        // ---- assembly: warp-per-real-element (warps 0..11) ----
        if (warp < 12) {
            const int e = warp;
            const int b = b0 + e;
            if (b < batch) {
                float qv = 0.f, dqv = 0.f, ddqv = 0.f;
                if (lane < 7) {
                    qv   = sm[MXIN + e * 24 + lane];
                    dqv  = sm[MXIN + e * 24 + 8 + lane];
                    ddqv = sm[MXIN + e * 24 + 16 + lane];
                }
                const float* scr = &sm[MA3 + (8 * e) * 30];
                float Lm[28];
#pragma unroll
                for (int t = 0; t < 28; t++) Lm[t] = scr[t];
                float sig[7];
#pragma unroll
                for (int r = 0; r < 7; r++) {
                    const int td = TRI(r, r);
                    const float p = Lm[td];
                    sig[r] = sigmf(p);
                    Lm[td] = softplusf(p);
                }
                float dLm[28];
                {
                    const int base = ((lane < 7) ? (1 + lane) : 1) * 30;
#pragma unroll
                    for (int t = 0; t < 28; t++) dLm[t] = scr[base + t];
#pragma unroll
                    for (int r = 0; r < 7; r++) dLm[TRI(r, r)] *= sig[r];
                }
                float dqs[7], dds[7];
#pragma unroll
                for (int r = 0; r < 7; r++) {
                    dqs[r] = __shfl_sync(FULL, dqv, r);
                    dds[r] = __shfl_sync(FULL, ddqv, r);
                }
                float u[7], t2[7];
#pragma unroll
                for (int c = 0; c < 7; c++) {
                    float s = 0.f, s2 = 0.f;
#pragma unroll
                    for (int r = 0; r < 7; r++) {
                        if (r >= c) {
                            const float lv = Lm[TRI(r, c)];
                            s = fmaf(lv, dqs[r], s);
                            s2 = fmaf(lv, dds[r], s2);
                        }
                    }
                    u[c] = s; t2[c] = s2;
                }
                float a[7], wv[7];
#pragma unroll
                for (int r = 0; r < 7; r++) {
                    float s = 0.f;
#pragma unroll
                    for (int c = 0; c < 7; c++) if (c <= r) s = fmaf(dLm[TRI(r, c)], u[c], s);
                    a[r] = s;
                }
#pragma unroll
                for (int c = 0; c < 7; c++) {
                    float s = 0.f;
#pragma unroll
                    for (int r = 0; r < 7; r++) if (r >= c) s = fmaf(dLm[TRI(r, c)], dqs[r], s);
                    wv[c] = s;
                }
                float wu = 0.f;
#pragma unroll
                for (int c = 0; c < 7; c++) wu = fmaf(wv[c], u[c], wu);

                const float dqj = (lane < 7) ? dqv : 0.f;
                float s1_sel = 0.f;
#pragma unroll
                for (int i = 0; i < 7; i++) {
                    float red = dqj * a[i];
                    red += __shfl_xor_sync(FULL, red, 4);
                    red += __shfl_xor_sync(FULL, red, 2);
                    red += __shfl_xor_sync(FULL, red, 1);
                    if (lane == i) s1_sel = red;
                }
                float Wred[7];
#pragma unroll
                for (int c = 0; c < 7; c++) {
                    float red = dqj * wv[c];
                    red += __shfl_xor_sync(FULL, red, 4);
                    red += __shfl_xor_sync(FULL, red, 2);
                    red += __shfl_xor_sync(FULL, red, 1);
                    Wred[c] = red;
                }
                float outsel = 0.f;
#pragma unroll
                for (int i = 0; i < 7; i++) {
                    float s = 0.f;
#pragma unroll
                    for (int c = 0; c <= i; c++) s = fmaf(Lm[TRI(i, c)], Wred[c] + t2[c], s);
                    if (lane == i) outsel = s;
                }
                if (lane < 7) out[b * 7 + lane] = outsel + s1_sel - wu;
            }
        }
        __syncthreads();
    }
}

// =====================================================================
// Kernel 2: damping + potential. 768 thr (24 warps, 3 groups of 8),
// tile = 96 elements, GVP scratch reuses dead H1.
// =====================================================================
#define D_W1T  0         // [i][16]: d0..13 = W1[d][i], [14]=b1[i]
#define D_W2P  2048      // [kp][i*2+p]
#define D_B2   18432
#define D_W3P  18560
#define D_B3   22144
#define D_PT   22176     // [h][8]: j0..6 = pW1[j][h], [7]=pb1[h]
#define D_SP2  23200
#define D_XIN  23328     // [96][17]
#define D_H1   24960     // [96][130]   (reused as GVP [96][65] after layer2)
#define D_H2   37440     // [96][130]
#define D_A3   49920     // [96][30]
#define D_GV   52800     // [96][8]
#define D_TOT  53568
#define D_GVP  D_H1

__global__ __launch_bounds__(768, 1) void k_damp(
    const float* __restrict__ q, const float* __restrict__ dq,
    const float* __restrict__ dW1, const float* __restrict__ db1,
    const float* __restrict__ dW2, const float* __restrict__ db2,
    const float* __restrict__ dW3, const float* __restrict__ db3,
    const float* __restrict__ pW1, const float* __restrict__ pb1,
    const float* __restrict__ pw2,
    float* __restrict__ out, int batch)
{
    extern __shared__ float sm[];
    const int tid = threadIdx.x;
    for (int idx = tid; idx < 2048; idx += 768) {
        const int i = idx >> 4, d = idx & 15;
        float v = 0.f;
        if (d < 14) v = dW1[d * 128 + i];
        else if (d == 14) v = db1[i];
        sm[D_W1T + idx] = v;
    }
    for (int idx = tid; idx < 16384; idx += 768) {
        const int kp = idx >> 8, r = idx & 255;
        sm[D_W2P + idx] = dW2[(2 * kp + (r & 1)) * 128 + (r >> 1)];
    }
    for (int idx = tid; idx < 3584; idx += 768) {
        const int kp = idx / 56, r = idx % 56;
        sm[D_W3P + idx] = dW3[(2 * kp + (r & 1)) * 28 + (r >> 1)];
    }
    for (int idx = tid; idx < 1024; idx += 768) {
        const int h = idx >> 3, j = idx & 7;
        sm[D_PT + idx] = (j < 7) ? pW1[j * 128 + h] : pb1[h];
    }
    for (int idx = tid; idx < 128; idx += 768) {
        sm[D_B2 + idx] = db2[idx];
        sm[D_SP2 + idx] = softplusf(pw2[idx]);
    }
    for (int idx = tid; idx < 32; idx += 768) sm[D_B3 + idx] = (idx < 28) ? db3[idx] : 0.f;
    __syncthreads();

    const int lane = tid & 31;
    const int warp = tid >> 5;       // 0..23
    const int grp  = warp >> 3;      // 0..2
    const int w    = warp & 7;       // output-slice within group
    const int el   = grp * 32 + lane; // element within tile (0..95)

    const int ntiles = (batch + 95) / 96;
    for (int tile = blockIdx.x; tile < ntiles; tile += gridDim.x) {
        const int b0 = tile * 96;
        // ---- stage inputs [e][0..6]=q, [7..13]=dq ----
        for (int idx = tid; idx < 96 * 14; idx += 768) {
            const int e = idx / 14, d = idx % 14;
            const int b = b0 + e;
            float v = 0.f;
            if (b < batch) v = (d < 7) ? q[b * 7 + d] : dq[b * 7 + d - 7];
            sm[D_XIN + e * 17 + d] = v;
        }
        __syncthreads();

        float xr[14];
#pragma unroll
        for (int d = 0; d < 14; d++) xr[d] = sm[D_XIN + el * 17 + d];

        // ---- layer 1 ----
#pragma unroll
        for (int ii = 0; ii < 16; ii++) {
            const int i = w * 16 + ii;
            const float4 r0 = *(const float4*)&sm[D_W1T + i * 16];
            const float4 r1 = *(const float4*)&sm[D_W1T + i * 16 + 4];
            const float4 r2 = *(const float4*)&sm[D_W1T + i * 16 + 8];
            const float4 r3 = *(const float4*)&sm[D_W1T + i * 16 + 12];
            float z = r3.z;
            z = fmaf(xr[0], r0.x, z);  z = fmaf(xr[1], r0.y, z);
            z = fmaf(xr[2], r0.z, z);  z = fmaf(xr[3], r0.w, z);
            z = fmaf(xr[4], r1.x, z);  z = fmaf(xr[5], r1.y, z);
            z = fmaf(xr[6], r1.z, z);  z = fmaf(xr[7], r1.w, z);
            z = fmaf(xr[8], r2.x, z);  z = fmaf(xr[9], r2.y, z);
            z = fmaf(xr[10], r2.z, z); z = fmaf(xr[11], r2.w, z);
            z = fmaf(xr[12], r3.x, z); z = fmaf(xr[13], r3.y, z);
            sm[D_H1 + el * 130 + i] = tanh_fast(z);
        }
        __syncthreads();

        // ---- layer 2 ----
        {
            ull acc[16];
#pragma unroll
            for (int ii = 0; ii < 16; ii++) acc[ii] = 0ull;
            const float* xrow = &sm[D_H1 + el * 130];
            const float* wbase = &sm[D_W2P + w * 32];
#pragma unroll 2
            for (int kp = 0; kp < 64; kp++) {
                const ull x2 = *(const ull*)(xrow + 2 * kp);
                const float* wr = wbase + kp * 256;
#pragma unroll
                for (int m = 0; m < 8; m++) {
                    const double2 wd = *(const double2*)(wr + 4 * m);
                    acc[2 * m]     = fma2(x2, __double_as_longlong(wd.x), acc[2 * m]);
                    acc[2 * m + 1] = fma2(x2, __double_as_longlong(wd.y), acc[2 * m + 1]);
                }
            }
#pragma unroll
            for (int ii = 0; ii < 16; ii++) {
                const int i = w * 16 + ii;
                sm[D_H2 + el * 130 + i] = tanh_fast(sum2(acc[ii]) + sm[D_B2 + i]);
            }
        }
        __syncthreads();

        // ---- layer 3 (warps w<7 per group) ----
        if (w < 7) {
            ull a4[4] = { 0ull, 0ull, 0ull, 0ull };
            const float* xrow = &sm[D_H2 + el * 130];
#pragma unroll 2
            for (int kp = 0; kp < 64; kp++) {
                const ull x2 = *(const ull*)(xrow + 2 * kp);
                const float* wr = &sm[D_W3P + kp * 56 + w * 8];
                const double2 w0 = *(const double2*)(wr);
                const double2 w1 = *(const double2*)(wr + 4);
                a4[0] = fma2(x2, __double_as_longlong(w0.x), a4[0]);
                a4[1] = fma2(x2, __double_as_longlong(w0.y), a4[1]);
                a4[2] = fma2(x2, __double_as_longlong(w1.x), a4[2]);
                a4[3] = fma2(x2, __double_as_longlong(w1.y), a4[3]);
            }
#pragma unroll
            for (int ii = 0; ii < 4; ii++) {
                const int i = w * 4 + ii;
                sm[D_A3 + el * 30 + i] = sum2(a4[ii]) + sm[D_B3 + i];
            }
        }
        // ---- gradV (all warps; H1 is dead, use as GVP) ----
        {
            float gp[7] = { 0.f, 0.f, 0.f, 0.f, 0.f, 0.f, 0.f };
            const int h0 = w * 16;
#pragma unroll
            for (int hh = 0; hh < 16; hh++) {
                const int h = h0 + hh;
                const float4 r0 = *(const float4*)&sm[D_PT + h * 8];
                const float4 r1 = *(const float4*)&sm[D_PT + h * 8 + 4];
                float z = r1.w;
                z = fmaf(xr[0], r0.x, z); z = fmaf(xr[1], r0.y, z);
                z = fmaf(xr[2], r0.z, z); z = fmaf(xr[3], r0.w, z);
                z = fmaf(xr[4], r1.x, z); z = fmaf(xr[5], r1.y, z);
                z = fmaf(xr[6], r1.z, z);
                const float s = sigmf(z) * sm[D_SP2 + h];
                gp[0] = fmaf(r0.x, s, gp[0]); gp[1] = fmaf(r0.y, s, gp[1]);
                gp[2] = fmaf(r0.z, s, gp[2]); gp[3] = fmaf(r0.w, s, gp[3]);
                gp[4] = fmaf(r1.x, s, gp[4]); gp[5] = fmaf(r1.y, s, gp[5]);
                gp[6] = fmaf(r1.z, s, gp[6]);
            }
#pragma unroll
            for (int j = 0; j < 7; j++) sm[D_GVP + el * 65 + w * 8 + j] = gp[j];
        }
        __syncthreads();

        // ---- reduce gradV partials ----
        if (tid < 672) {
            const int e = tid / 7, j = tid % 7;
            float s = 0.f;
#pragma unroll
            for (int ww = 0; ww < 8; ww++) s += sm[D_GVP + e * 65 + ww * 8 + j];
            sm[D_GV + e * 8 + j] = s;
        }
        __syncthreads();

        // ---- assembly: warps with w==0, lane = element in group ----
        if (w == 0) {
            const int b = b0 + el;
            if (b < batch) {
                float Lm[28];
#pragma unroll
                for (int t = 0; t < 28; t++) Lm[t] = sm[D_A3 + el * 30 + t];
#pragma unroll
                for (int r = 0; r < 7; r++) Lm[TRI(r, r)] = softplusf(Lm[TRI(r, r)]);
                float u[7];
#pragma unroll
                for (int c = 0; c < 7; c++) {
                    float s = 0.f;
#pragma unroll
                    for (int r = 0; r < 7; r++)
                        if (r >= c) s = fmaf(Lm[TRI(r, c)], xr[7 + r], s);
                    u[c] = s;
                }
                const int ob = b * 7;
#pragma unroll
                for (int i = 0; i < 7; i++) {
                    float s = sm[D_GV + el * 8 + i];
#pragma unroll
                    for (int c = 0; c < 7; c++)
                        if (c <= i) s = fmaf(Lm[TRI(i, c)], u[c], s);
                    out[ob + i] += s;
                }
            }
        }
        __syncthreads();
    }
}

// =====================================================================
extern "C" void kernel_launch(void* const* d_in, const int* in_sizes, int n_in,
                              void* d_out, int out_size)
{
    const float* q   = (const float*)d_in[0];
    const float* dq  = (const float*)d_in[1];
    const float* ddq = (const float*)d_in[2];
    const float* mW1 = (const float*)d_in[3];
    const float* mb1 = (const float*)d_in[4];
    const float* mW2 = (const float*)d_in[5];
    const float* mb2 = (const float*)d_in[6];
    const float* mW3 = (const float*)d_in[7];
    const float* mb3 = (const float*)d_in[8];
    const float* dW1 = (const float*)d_in[9];
    const float* db1 = (const float*)d_in[10];
    const float* dW2 = (const float*)d_in[11];
    const float* db2 = (const float*)d_in[12];
    const float* dW3 = (const float*)d_in[13];
    const float* db3 = (const float*)d_in[14];
    const float* pW1 = (const float*)d_in[15];
    const float* pb1 = (const float*)d_in[16];
    const float* pw2 = (const float*)d_in[17];
    float* out = (float*)d_out;

    const int batch = in_sizes[0] / 7;

    const size_t sm1 = (size_t)M_TOT * sizeof(float);
    const size_t sm2 = (size_t)D_TOT * sizeof(float);

    cudaFuncSetAttribute(k_mass, cudaFuncAttributeMaxDynamicSharedMemorySize, (int)sm1);
    cudaFuncSetAttribute(k_damp, cudaFuncAttributeMaxDynamicSharedMemorySize, (int)sm2);

    k_mass<<<148, 768, sm1>>>(q, dq, ddq, mW1, mb1, mW2, mb2, mW3, mb3, out, batch);
    k_damp<<<148, 768, sm2>>>(q, dq, dW1, db1, dW2, db2, dW3, db3, pW1, pb1, pw2, out, batch);
}

// round 7
// speedup vs baseline: 1.1864x; 1.1864x over previous
#include <cuda_runtime.h>
#include <math.h>

#define FULL 0xffffffffu
typedef unsigned long long ull;

static __device__ __forceinline__ float softplusf(float x) {
    return fmaxf(x, 0.f) + log1pf(expf(-fabsf(x)));
}
static __device__ __forceinline__ float sigmf(float x) {
    return __fdividef(1.f, 1.f + __expf(-x));
}
static __device__ __forceinline__ float tanh_fast(float x) {
    const float e = __expf(2.f * x);
    return 1.f - __fdividef(2.f, e + 1.f);
}
__host__ __device__ constexpr int TRI(int r, int c) { return r * (r + 1) / 2 + c; }

static __device__ __forceinline__ ull fma2(ull a, ull b, ull c) {
    ull d;
    asm("fma.rn.f32x2 %0, %1, %2, %3;" : "=l"(d) : "l"(a), "l"(b), "l"(c));
    return d;
}
static __device__ __forceinline__ float sum2(ull v) {
    unsigned l, h;
    asm("mov.b64 {%0, %1}, %2;" : "=r"(l), "=r"(h) : "l"(v));
    return __uint_as_float(l) + __uint_as_float(h);
}
static __device__ __forceinline__ ull packf2(float lo, float hi) {
    ull d;
    asm("mov.b64 %0, {%1, %2};" : "=l"(d) : "r"(__float_as_uint(lo)), "r"(__float_as_uint(hi)));
    return d;
}

// =====================================================================
// Kernel 1: mass + Coriolis. 512 thr, 16 warps.
// Tile = 16 elements = 128 rows (row = ve = 8e+v).
// Layer2/3: warp = (outslice, rowhalf); lane owns 2 rows.
// =====================================================================
#define MW1   0         // [7][128]
#define MB1   896
#define MW2P  1024      // [kp][2i+p]  64*256
#define MB2   17408
#define MW3P  17536     // [kp][2i+p]  64*56
#define MB3   21120     // 32
#define MXIN  21152     // [16][24]
#define MH1   21536     // [128][130]  (A3 overlay: [128][33])
#define MH2   38176     // [128][130]
#define M_TOT 54816
#define MA3   MH1

__global__ __launch_bounds__(512, 1) void k_mass(
    const float* __restrict__ q, const float* __restrict__ dq, const float* __restrict__ ddq,
    const float* __restrict__ mW1, const float* __restrict__ mb1,
    const float* __restrict__ mW2, const float* __restrict__ mb2,
    const float* __restrict__ mW3, const float* __restrict__ mb3,
    float* __restrict__ out, int batch)
{
    extern __shared__ float sm[];
    const int tid = threadIdx.x;
    for (int i = tid; i < 896; i += 512) sm[MW1 + i] = mW1[i];
    for (int i = tid; i < 128; i += 512) { sm[MB1 + i] = mb1[i]; sm[MB2 + i] = mb2[i]; }
    for (int idx = tid; idx < 16384; idx += 512) {
        const int kp = idx >> 8, r = idx & 255;
        sm[MW2P + idx] = mW2[(2 * kp + (r & 1)) * 128 + (r >> 1)];
    }
    for (int idx = tid; idx < 3584; idx += 512) {
        const int kp = idx / 56, r = idx % 56;
        sm[MW3P + idx] = mW3[(2 * kp + (r & 1)) * 28 + (r >> 1)];
    }
    for (int i = tid; i < 32; i += 512) sm[MB3 + i] = (i < 28) ? mb3[i] : 0.f;
    __syncthreads();

    const int lane = tid & 31;
    const int warp = tid >> 5;       // 0..15
    const int o    = warp & 7;       // layer2 outslice / layer3 outquad
    const int rh   = warp >> 3;      // rowhalf
    const int R0   = rh * 64 + lane;
    const int R1   = R0 + 32;
    const bool isv0 = (lane & 7) == 0;
    const int srcl = lane & 24;

    // layer1 per-thread weights (i fixed)
    const int i1 = tid & 127;
    const int eoff = tid >> 7;       // 0..3
    float w1r[7];
#pragma unroll
    for (int d = 0; d < 7; d++) w1r[d] = sm[MW1 + d * 128 + i1];
    const float b1r = sm[MB1 + i1];

    const int ntiles = (batch + 15) >> 4;
    for (int tile = blockIdx.x; tile < ntiles; tile += gridDim.x) {
        const int b0 = tile << 4;

        // ---- stage inputs [16][24] ----
        for (int idx = tid; idx < 384; idx += 512) {
            const int e = idx / 24, s = idx % 24;
            const int b = b0 + e;
            float v = 0.f;
            if (b < batch) {
                if (s < 7) v = q[b * 7 + s];
                else if (s >= 8 && s < 15) v = dq[b * 7 + s - 8];
                else if (s >= 16 && s < 23) v = ddq[b * 7 + s - 16];
            }
            sm[MXIN + idx] = v;
        }
        __syncthreads();

        // ---- layer 1 + tangent seed ----
#pragma unroll
        for (int it = 0; it < 4; it++) {
            const int e = eoff * 4 + it;
            float z = b1r;
#pragma unroll
            for (int d = 0; d < 7; d++) z = fmaf(sm[MXIN + e * 24 + d], w1r[d], z);
            const float h = tanh_fast(z);
            const float g = 1.f - h * h;
            float* base = &sm[MH1 + (8 * e) * 130 + i1];
            base[0] = h;
#pragma unroll
            for (int v = 0; v < 7; v++) base[(v + 1) * 130] = g * w1r[v];
        }
        __syncthreads();

        // ---- layer 2: 16 outs x 2 rows per lane ----
        {
            ull acc0[16], acc1[16];
#pragma unroll
            for (int ii = 0; ii < 16; ii++) { acc0[ii] = 0ull; acc1[ii] = 0ull; }
            const float* x0 = &sm[MH1 + R0 * 130];
            const float* x1 = &sm[MH1 + R1 * 130];
            const float* wb = &sm[MW2P + o * 32];
#pragma unroll 1
            for (int kp = 0; kp < 64; kp++) {
                const ull xa = *(const ull*)(x0 + 2 * kp);
                const ull xb = *(const ull*)(x1 + 2 * kp);
                const float* wr = wb + kp * 256;
#pragma unroll
                for (int m = 0; m < 8; m++) {
                    const double2 wd = *(const double2*)(wr + 4 * m);
                    const ull wx = __double_as_longlong(wd.x);
                    const ull wy = __double_as_longlong(wd.y);
                    acc0[2 * m]     = fma2(xa, wx, acc0[2 * m]);
                    acc1[2 * m]     = fma2(xb, wx, acc1[2 * m]);
                    acc0[2 * m + 1] = fma2(xa, wy, acc0[2 * m + 1]);
                    acc1[2 * m + 1] = fma2(xb, wy, acc1[2 * m + 1]);
                }
            }
            float z0v[16], z1v[16], g0v[16], g1v[16];
#pragma unroll
            for (int ii = 0; ii < 16; ii++) { z0v[ii] = sum2(acc0[ii]); z1v[ii] = sum2(acc1[ii]); }
            if (isv0) {
#pragma unroll
                for (int ii = 0; ii < 16; ii++) {
                    const float bb = sm[MB2 + o * 16 + ii];
                    const float h0 = tanh_fast(z0v[ii] + bb);
                    const float h1 = tanh_fast(z1v[ii] + bb);
                    g0v[ii] = 1.f - h0 * h0;
                    g1v[ii] = 1.f - h1 * h1;
                    z0v[ii] = h0; z1v[ii] = h1;
                }
            }
            float* y0 = &sm[MH2 + R0 * 130 + o * 16];
            float* y1 = &sm[MH2 + R1 * 130 + o * 16];
#pragma unroll
            for (int m = 0; m < 8; m++) {
                const float gs0a = __shfl_sync(FULL, g0v[2 * m], srcl);
                const float gs0b = __shfl_sync(FULL, g0v[2 * m + 1], srcl);
                const float gs1a = __shfl_sync(FULL, g1v[2 * m], srcl);
                const float gs1b = __shfl_sync(FULL, g1v[2 * m + 1], srcl);
                const float v0a = isv0 ? z0v[2 * m] : gs0a * z0v[2 * m];
                const float v0b = isv0 ? z0v[2 * m + 1] : gs0b * z0v[2 * m + 1];
                const float v1a = isv0 ? z1v[2 * m] : gs1a * z1v[2 * m];
                const float v1b = isv0 ? z1v[2 * m + 1] : gs1b * z1v[2 * m + 1];
                *(ull*)(y0 + 2 * m) = packf2(v0a, v0b);
                *(ull*)(y1 + 2 * m) = packf2(v1a, v1b);
            }
        }
        __syncthreads();

        // ---- layer 3: warps o<7 own 4 outs; 2 rows per lane ----
        if (o < 7) {
            ull a0[4] = {0,0,0,0}, a1[4] = {0,0,0,0};
            const float* x0 = &sm[MH2 + R0 * 130];
            const float* x1 = &sm[MH2 + R1 * 130];
#pragma unroll 1
            for (int kp = 0; kp < 64; kp++) {
                const ull xa = *(const ull*)(x0 + 2 * kp);
                const ull xb = *(const ull*)(x1 + 2 * kp);
                const float* wr = &sm[MW3P + kp * 56 + o * 8];
                const double2 w0 = *(const double2*)(wr);
                const double2 w1 = *(const double2*)(wr + 4);
                const ull wA = __double_as_longlong(w0.x), wB = __double_as_longlong(w0.y);
                const ull wC = __double_as_longlong(w1.x), wD = __double_as_longlong(w1.y);
                a0[0] = fma2(xa, wA, a0[0]); a1[0] = fma2(xb, wA, a1[0]);
                a0[1] = fma2(xa, wB, a0[1]); a1[1] = fma2(xb, wB, a1[1]);
                a0[2] = fma2(xa, wC, a0[2]); a1[2] = fma2(xb, wC, a1[2]);
                a0[3] = fma2(xa, wD, a0[3]); a1[3] = fma2(xb, wD, a1[3]);
            }
#pragma unroll
            for (int j = 0; j < 4; j++) {
                const int i = o * 4 + j;
                const float bb = isv0 ? sm[MB3 + i] : 0.f;
                sm[MA3 + R0 * 33 + i] = sum2(a0[j]) + bb;
                sm[MA3 + R1 * 33 + i] = sum2(a1[j]) + bb;
            }
        }
        __syncthreads();

        // ---- assembly: warp-per-element ----
        {
            const int e = warp;
            const int b = b0 + e;
            if (b < batch) {
                float qv = 0.f, dqv = 0.f, ddqv = 0.f;
                if (lane < 7) {
                    qv   = sm[MXIN + e * 24 + lane];
                    dqv  = sm[MXIN + e * 24 + 8 + lane];
                    ddqv = sm[MXIN + e * 24 + 16 + lane];
                }
                const float* scr = &sm[MA3 + (8 * e) * 33];
                float Lm[28];
#pragma unroll
                for (int t = 0; t < 28; t++) Lm[t] = scr[t];
                float sig[7];
#pragma unroll
                for (int r = 0; r < 7; r++) {
                    const int td = TRI(r, r);
                    const float p = Lm[td];
                    sig[r] = sigmf(p);
                    Lm[td] = softplusf(p);
                }
                float dLm[28];
                {
                    const float* dbase = scr + ((lane < 7) ? (1 + lane) : 1) * 33;
#pragma unroll
                    for (int t = 0; t < 28; t++) dLm[t] = dbase[t];
#pragma unroll
                    for (int r = 0; r < 7; r++) dLm[TRI(r, r)] *= sig[r];
                }
                float dqs[7], dds[7];
#pragma unroll
                for (int r = 0; r < 7; r++) {
                    dqs[r] = __shfl_sync(FULL, dqv, r);
                    dds[r] = __shfl_sync(FULL, ddqv, r);
                }
                float u[7], t2[7];
#pragma unroll
                for (int c = 0; c < 7; c++) {
                    float s = 0.f, s2 = 0.f;
#pragma unroll
                    for (int r = 0; r < 7; r++) {
                        if (r >= c) {
                            const float lv = Lm[TRI(r, c)];
                            s = fmaf(lv, dqs[r], s);
                            s2 = fmaf(lv, dds[r], s2);
                        }
                    }
                    u[c] = s; t2[c] = s2;
                }
                float a[7], w[7];
#pragma unroll
                for (int r = 0; r < 7; r++) {
                    float s = 0.f;
#pragma unroll
                    for (int c = 0; c < 7; c++) if (c <= r) s = fmaf(dLm[TRI(r, c)], u[c], s);
                    a[r] = s;
                }
#pragma unroll
                for (int c = 0; c < 7; c++) {
                    float s = 0.f;
#pragma unroll
                    for (int r = 0; r < 7; r++) if (r >= c) s = fmaf(dLm[TRI(r, c)], dqs[r], s);
                    w[c] = s;
                }
                float wu = 0.f;
#pragma unroll
                for (int c = 0; c < 7; c++) wu = fmaf(w[c], u[c], wu);

                const float dqj = (lane < 7) ? dqv : 0.f;
                float s1_sel = 0.f;
#pragma unroll
                for (int i = 0; i < 7; i++) {
                    float red = dqj * a[i];
                    red += __shfl_xor_sync(FULL, red, 4);
                    red += __shfl_xor_sync(FULL, red, 2);
                    red += __shfl_xor_sync(FULL, red, 1);
                    if (lane == i) s1_sel = red;
                }
                float Wred[7];
#pragma unroll
                for (int c = 0; c < 7; c++) {
                    float red = dqj * w[c];
                    red += __shfl_xor_sync(FULL, red, 4);
                    red += __shfl_xor_sync(FULL, red, 2);
                    red += __shfl_xor_sync(FULL, red, 1);
                    Wred[c] = red;
                }
                float outsel = 0.f;
#pragma unroll
                for (int i = 0; i < 7; i++) {
                    float s = 0.f;
#pragma unroll
                    for (int c = 0; c <= i; c++) s = fmaf(Lm[TRI(i, c)], Wred[c] + t2[c], s);
                    if (lane == i) outsel = s;
                }
                if (lane < 7) out[b * 7 + lane] = outsel + s1_sel - wu;
            }
        }
        __syncthreads();
    }
}

// =====================================================================
// Kernel 2: damping + potential. 512 thr, 16 warps.
// Tile = 128 elements = 128 rows. gradV fused into assembly.
// =====================================================================
#define DW1   0         // [14][128]
#define DB1   1792
#define DW2P  1920
#define DB2   18304
#define DW3P  18432
#define DB3   22016     // 32
#define DPT   22048     // [h][8]
#define DSP2  23072
#define DH1   23200     // [128][130] (A3 overlay [128][33])
#define DH2   39840     // [128][130] (XIN overlay [128][14] during layer1)
#define D_TOT 56480
#define DA3   DH1
#define DXIN  DH2

__global__ __launch_bounds__(512, 1) void k_damp(
    const float* __restrict__ q, const float* __restrict__ dq,
    const float* __restrict__ dW1, const float* __restrict__ db1,
    const float* __restrict__ dW2, const float* __restrict__ db2,
    const float* __restrict__ dW3, const float* __restrict__ db3,
    const float* __restrict__ pW1, const float* __restrict__ pb1,
    const float* __restrict__ pw2,
    float* __restrict__ out, int batch)
{
    extern __shared__ float sm[];
    const int tid = threadIdx.x;
    for (int i = tid; i < 1792; i += 512) sm[DW1 + i] = dW1[i];
    for (int i = tid; i < 128; i += 512) {
        sm[DB1 + i] = db1[i]; sm[DB2 + i] = db2[i]; sm[DSP2 + i] = softplusf(pw2[i]);
    }
    for (int idx = tid; idx < 16384; idx += 512) {
        const int kp = idx >> 8, r = idx & 255;
        sm[DW2P + idx] = dW2[(2 * kp + (r & 1)) * 128 + (r >> 1)];
    }
    for (int idx = tid; idx < 3584; idx += 512) {
        const int kp = idx / 56, r = idx % 56;
        sm[DW3P + idx] = dW3[(2 * kp + (r & 1)) * 28 + (r >> 1)];
    }
    for (int idx = tid; idx < 1024; idx += 512) {
        const int h = idx >> 3, j = idx & 7;
        sm[DPT + idx] = (j < 7) ? pW1[j * 128 + h] : pb1[h];
    }
    for (int i = tid; i < 32; i += 512) sm[DB3 + i] = (i < 28) ? db3[i] : 0.f;
    __syncthreads();

    const int lane = tid & 31;
    const int warp = tid >> 5;
    const int o    = warp & 7;
    const int rh   = warp >> 3;
    const int R0   = rh * 64 + lane;
    const int R1   = R0 + 32;

    // layer1 per-thread weights
    const int i1 = tid & 127;
    const int eg = tid >> 7;     // 0..3
    float w1r[14];
#pragma unroll
    for (int d = 0; d < 14; d++) w1r[d] = sm[DW1 + d * 128 + i1];
    const float b1r = sm[DB1 + i1];

    const int ntiles = (batch + 127) >> 7;
    for (int tile = blockIdx.x; tile < ntiles; tile += gridDim.x) {
        const int b0 = tile << 7;

        // ---- stage XIN [128][14] (in H2 region) ----
        for (int idx = tid; idx < 1792; idx += 512) {
            const int e = idx / 14, d = idx % 14;
            const int b = b0 + e;
            float v = 0.f;
            if (b < batch) v = (d < 7) ? q[b * 7 + d] : dq[b * 7 + d - 7];
            sm[DXIN + idx] = v;
        }
        __syncthreads();

        // ---- layer 1 ----
#pragma unroll 2
        for (int it = 0; it < 32; it++) {
            const int e = eg * 32 + it;
            const float* xe = &sm[DXIN + e * 14];
            float z = b1r;
#pragma unroll
            for (int d = 0; d < 14; d++) z = fmaf(xe[d], w1r[d], z);
            sm[DH1 + e * 130 + i1] = tanh_fast(z);
        }
        __syncthreads();

        // ---- layer 2 ----
        {
            ull acc0[16], acc1[16];
#pragma unroll
            for (int ii = 0; ii < 16; ii++) { acc0[ii] = 0ull; acc1[ii] = 0ull; }
            const float* x0 = &sm[DH1 + R0 * 130];
            const float* x1 = &sm[DH1 + R1 * 130];
            const float* wb = &sm[DW2P + o * 32];
#pragma unroll 1
            for (int kp = 0; kp < 64; kp++) {
                const ull xa = *(const ull*)(x0 + 2 * kp);
                const ull xb = *(const ull*)(x1 + 2 * kp);
                const float* wr = wb + kp * 256;
#pragma unroll
                for (int m = 0; m < 8; m++) {
                    const double2 wd = *(const double2*)(wr + 4 * m);
                    const ull wx = __double_as_longlong(wd.x);
                    const ull wy = __double_as_longlong(wd.y);
                    acc0[2 * m]     = fma2(xa, wx, acc0[2 * m]);
                    acc1[2 * m]     = fma2(xb, wx, acc1[2 * m]);
                    acc0[2 * m + 1] = fma2(xa, wy, acc0[2 * m + 1]);
                    acc1[2 * m + 1] = fma2(xb, wy, acc1[2 * m + 1]);
                }
            }
            float* y0 = &sm[DH2 + R0 * 130 + o * 16];
            float* y1 = &sm[DH2 + R1 * 130 + o * 16];
#pragma unroll
            for (int m = 0; m < 8; m++) {
                const float ba = sm[DB2 + o * 16 + 2 * m];
                const float bb = sm[DB2 + o * 16 + 2 * m + 1];
                const float v0a = tanh_fast(sum2(acc0[2 * m]) + ba);
                const float v0b = tanh_fast(sum2(acc0[2 * m + 1]) + bb);
                const float v1a = tanh_fast(sum2(acc1[2 * m]) + ba);
                const float v1b = tanh_fast(sum2(acc1[2 * m + 1]) + bb);
                *(ull*)(y0 + 2 * m) = packf2(v0a, v0b);
                *(ull*)(y1 + 2 * m) = packf2(v1a, v1b);
            }
        }
        __syncthreads();

        // ---- layer 3 ----
        if (o < 7) {
            ull a0[4] = {0,0,0,0}, a1[4] = {0,0,0,0};
            const float* x0 = &sm[DH2 + R0 * 130];
            const float* x1 = &sm[DH2 + R1 * 130];
#pragma unroll 1
            for (int kp = 0; kp < 64; kp++) {
                const ull xa = *(const ull*)(x0 + 2 * kp);
                const ull xb = *(const ull*)(x1 + 2 * kp);
                const float* wr = &sm[DW3P + kp * 56 + o * 8];
                const double2 w0 = *(const double2*)(wr);
                const double2 w1 = *(const double2*)(wr + 4);
                const ull wA = __double_as_longlong(w0.x), wB = __double_as_longlong(w0.y);
                const ull wC = __double_as_longlong(w1.x), wD = __double_as_longlong(w1.y);
                a0[0] = fma2(xa, wA, a0[0]); a1[0] = fma2(xb, wA, a1[0]);
                a0[1] = fma2(xa, wB, a0[1]); a1[1] = fma2(xb, wB, a1[1]);
                a0[2] = fma2(xa, wC, a0[2]); a1[2] = fma2(xb, wC, a1[2]);
                a0[3] = fma2(xa, wD, a0[3]); a1[3] = fma2(xb, wD, a1[3]);
            }
#pragma unroll
            for (int j = 0; j < 4; j++) {
                const int i = o * 4 + j;
                const float bb = sm[DB3 + i];
                sm[DA3 + R0 * 33 + i] = sum2(a0[j]) + bb;
                sm[DA3 + R1 * 33 + i] = sum2(a1[j]) + bb;
            }
        }
        __syncthreads();

        // ---- assembly + gradV: warp-per-element, 8 rounds ----
#pragma unroll 1
        for (int rr = 0; rr < 8; rr++) {
            const int e = rr * 16 + warp;
            const int b = b0 + e;
            if (b < batch) {
                float qv = 0.f, dqv = 0.f;
                if (lane < 7) { qv = q[b * 7 + lane]; dqv = dq[b * 7 + lane]; }
                float qs[7], dqs[7];
#pragma unroll
                for (int r = 0; r < 7; r++) {
                    qs[r] = __shfl_sync(FULL, qv, r);
                    dqs[r] = __shfl_sync(FULL, dqv, r);
                }
                // gradV partials: 4 h per lane
                float gp[7] = {0.f,0.f,0.f,0.f,0.f,0.f,0.f};
#pragma unroll
                for (int hh = 0; hh < 4; hh++) {
                    const int h = hh * 32 + lane;
                    const float4 r0 = *(const float4*)&sm[DPT + h * 8];
                    const float4 r1 = *(const float4*)&sm[DPT + h * 8 + 4];
                    float z = r1.w;
                    z = fmaf(qs[0], r0.x, z); z = fmaf(qs[1], r0.y, z);
                    z = fmaf(qs[2], r0.z, z); z = fmaf(qs[3], r0.w, z);
                    z = fmaf(qs[4], r1.x, z); z = fmaf(qs[5], r1.y, z);
                    z = fmaf(qs[6], r1.z, z);
                    const float s = sigmf(z) * sm[DSP2 + h];
                    gp[0] = fmaf(r0.x, s, gp[0]); gp[1] = fmaf(r0.y, s, gp[1]);
                    gp[2] = fmaf(r0.z, s, gp[2]); gp[3] = fmaf(r0.w, s, gp[3]);
                    gp[4] = fmaf(r1.x, s, gp[4]); gp[5] = fmaf(r1.y, s, gp[5]);
                    gp[6] = fmaf(r1.z, s, gp[6]);
                }
#pragma unroll
                for (int j = 0; j < 7; j++) {
                    gp[j] += __shfl_xor_sync(FULL, gp[j], 16);
                    gp[j] += __shfl_xor_sync(FULL, gp[j], 8);
                    gp[j] += __shfl_xor_sync(FULL, gp[j], 4);
                    gp[j] += __shfl_xor_sync(FULL, gp[j], 2);
                    gp[j] += __shfl_xor_sync(FULL, gp[j], 1);
                }
                // damping Cholesky
                const float* scr = &sm[DA3 + e * 33];
                float Lm[28];
#pragma unroll
                for (int t = 0; t < 28; t++) Lm[t] = scr[t];
#pragma unroll
                for (int r = 0; r < 7; r++) Lm[TRI(r, r)] = softplusf(Lm[TRI(r, r)]);
                float u[7];
#pragma unroll
                for (int c = 0; c < 7; c++) {
                    float s = 0.f;
#pragma unroll
                    for (int r = 0; r < 7; r++)
                        if (r >= c) s = fmaf(Lm[TRI(r, c)], dqs[r], s);
                    u[c] = s;
                }
                float outsel = 0.f;
#pragma unroll
                for (int i = 0; i < 7; i++) {
                    float s = gp[i];
#pragma unroll
                    for (int c = 0; c <= i; c++) s = fmaf(Lm[TRI(i, c)], u[c], s);
                    if (lane == i) outsel = s;
                }
                if (lane < 7) out[b * 7 + lane] += outsel;
            }
        }
        __syncthreads();
    }
}

// =====================================================================
extern "C" void kernel_launch(void* const* d_in, const int* in_sizes, int n_in,
                              void* d_out, int out_size)
{
    const float* q   = (const float*)d_in[0];
    const float* dq  = (const float*)d_in[1];
    const float* ddq = (const float*)d_in[2];
    const float* mW1 = (const float*)d_in[3];
    const float* mb1 = (const float*)d_in[4];
    const float* mW2 = (const float*)d_in[5];
    const float* mb2 = (const float*)d_in[6];
    const float* mW3 = (const float*)d_in[7];
    const float* mb3 = (const float*)d_in[8];
    const float* dW1 = (const float*)d_in[9];
    const float* db1 = (const float*)d_in[10];
    const float* dW2 = (const float*)d_in[11];
    const float* db2 = (const float*)d_in[12];
    const float* dW3 = (const float*)d_in[13];
    const float* db3 = (const float*)d_in[14];
    const float* pW1 = (const float*)d_in[15];
    const float* pb1 = (const float*)d_in[16];
    const float* pw2 = (const float*)d_in[17];
    float* out = (float*)d_out;

    const int batch = in_sizes[0] / 7;

    const size_t sm1 = (size_t)M_TOT * sizeof(float);
    const size_t sm2 = (size_t)D_TOT * sizeof(float);

    cudaFuncSetAttribute(k_mass, cudaFuncAttributeMaxDynamicSharedMemorySize, (int)sm1);
    cudaFuncSetAttribute(k_damp, cudaFuncAttributeMaxDynamicSharedMemorySize, (int)sm2);

    k_mass<<<148, 512, sm1>>>(q, dq, ddq, mW1, mb1, mW2, mb2, mW3, mb3, out, batch);
    k_damp<<<148, 512, sm2>>>(q, dq, dW1, db1, dW2, db2, dW3, db3, pW1, pb1, pw2, out, batch);
}

// round 10
// speedup vs baseline: 1.9932x; 1.6800x over previous
#include <cuda_runtime.h>
#include <math.h>

#define FULL 0xffffffffu
typedef unsigned long long ull;
typedef unsigned int u32;

static __device__ __forceinline__ float softplusf(float x) {
    return fmaxf(x, 0.f) + log1pf(expf(-fabsf(x)));
}
static __device__ __forceinline__ float sigmf(float x) {
    return __fdividef(1.f, 1.f + __expf(-x));
}
static __device__ __forceinline__ float tanh_fast(float x) {
    const float e = __expf(2.f * x);
    return 1.f - __fdividef(2.f, e + 1.f);
}
__host__ __device__ constexpr int TRI(int r, int c) { return r * (r + 1) / 2 + c; }

static __device__ __forceinline__ ull fma2(ull a, ull b, ull c) {
    ull d;
    asm("fma.rn.f32x2 %0, %1, %2, %3;" : "=l"(d) : "l"(a), "l"(b), "l"(c));
    return d;
}
static __device__ __forceinline__ float sum2(ull v) {
    u32 l, h;
    asm("mov.b64 {%0, %1}, %2;" : "=r"(l), "=r"(h) : "l"(v));
    return __uint_as_float(l) + __uint_as_float(h);
}
static __device__ __forceinline__ void unpk2(ull v, float& a, float& b) {
    u32 l, h;
    asm("mov.b64 {%0, %1}, %2;" : "=r"(l), "=r"(h) : "l"(v));
    a = __uint_as_float(l); b = __uint_as_float(h);
}
static __device__ __forceinline__ ull packf2(float lo, float hi) {
    ull d;
    asm("mov.b64 %0, {%1, %2};" : "=l"(d) : "r"(__float_as_uint(lo)), "r"(__float_as_uint(hi)));
    return d;
}

// =====================================================================
// k_mass: JVP+VJP formulation. Tile = 32 elements, 64 fwd rows
// (row 2e = primal, 2e+1 = dq-tangent). 512 thr, 16 warps.
// Pair-major W2P/W3P serve forward (pair-mult) AND backward (splat-mult).
// =====================================================================
#define MW1   0        // [7][128]
#define MB1   896
#define MB2   1024
#define MB3   1152
#define W2P   1184     // [kp64][2i+p] -> 17568
#define W3P   17568    // [ip64][2t+p] -> 21152
#define MXIN  21152    // [32][24] -> 21920
#define MH1   21920    // [64][130] -> 30240
#define MH2   30240    // [64][130] -> 38560
#define MA3   38560    // [64][30] -> 40480
#define MGH   40480    // [32][30] -> 41440
#define MTA   41440    // [32][8]  -> 41696
#define BZ2   41696    // [32][130] -> 45856
#define BZ1   45856    // [32][130] -> 50016
#define M_TOT 50016

__global__ __launch_bounds__(512, 1) void k_mass(
    const float* __restrict__ q, const float* __restrict__ dq, const float* __restrict__ ddq,
    const float* __restrict__ mW1, const float* __restrict__ mb1,
    const float* __restrict__ mW2, const float* __restrict__ mb2,
    const float* __restrict__ mW3, const float* __restrict__ mb3,
    float* __restrict__ out, int batch)
{
    extern __shared__ float smf[];
    const int tid = threadIdx.x;
    const int lane = tid & 31;
    const int warp = tid >> 5;

    for (int i = tid; i < 896; i += 512) smf[MW1 + i] = mW1[i];
    for (int i = tid; i < 128; i += 512) { smf[MB1 + i] = mb1[i]; smf[MB2 + i] = mb2[i]; }
    for (int i = tid; i < 32; i += 512) smf[MB3 + i] = (i < 28) ? mb3[i] : 0.f;
    for (int idx = tid; idx < 16384; idx += 512) {
        const int kp = idx >> 8, r = idx & 255;
        smf[W2P + idx] = mW2[(2 * kp + (r & 1)) * 128 + (r >> 1)];
    }
    for (int idx = tid; idx < 3584; idx += 512) {
        const int kp = idx / 56, r = idx % 56;
        smf[W3P + idx] = mW3[(2 * kp + (r & 1)) * 28 + (r >> 1)];
    }
    __syncthreads();

    const int i1 = tid & 127;
    const int eg = tid >> 7;
    float w1r[7];
#pragma unroll
    for (int d = 0; d < 7; d++) w1r[d] = smf[MW1 + d * 128 + i1];
    const float b1r = smf[MB1 + i1];

    const int ntiles = (batch + 31) >> 5;
    for (int tile = blockIdx.x; tile < ntiles; tile += gridDim.x) {
        const int b0 = tile << 5;

        // 1. stage XIN
        for (int idx = tid; idx < 768; idx += 512) {
            const int e = idx / 24, s = idx % 24;
            const int b = b0 + e;
            float v = 0.f;
            if (b < batch) {
                if (s < 7) v = q[b * 7 + s];
                else if (s >= 8 && s < 15) v = dq[b * 7 + s - 8];
                else if (s >= 16 && s < 23) v = ddq[b * 7 + s - 16];
            }
            smf[MXIN + idx] = v;
        }
        __syncthreads();

        // 2. layer1 primal + tangent
#pragma unroll
        for (int it = 0; it < 8; it++) {
            const int e = eg * 8 + it;
            const float* xe = &smf[MXIN + e * 24];
            float z = b1r, dz = 0.f;
#pragma unroll
            for (int d = 0; d < 7; d++) {
                z = fmaf(xe[d], w1r[d], z);
                dz = fmaf(xe[8 + d], w1r[d], dz);
            }
            const float h = tanh_fast(z);
            smf[MH1 + (2 * e) * 130 + i1] = h;
            smf[MH1 + (2 * e + 1) * 130 + i1] = (1.f - h * h) * dz;
        }
        __syncthreads();

        // 3. fwd L2: warp->8 outs, lane rows (lane, lane+32)
        {
            ull acc[16];
#pragma unroll
            for (int m = 0; m < 16; m++) acc[m] = 0ull;
            const float* x0 = &smf[MH1 + lane * 130];
            const float* x1 = &smf[MH1 + (lane + 32) * 130];
            const float* wb = &smf[W2P + warp * 16];
#pragma unroll 2
            for (int kp = 0; kp < 64; kp++) {
                const ull xa = *(const ull*)(x0 + 2 * kp);
                const ull xb = *(const ull*)(x1 + 2 * kp);
                const float* wr = wb + kp * 256;
#pragma unroll
                for (int m = 0; m < 4; m++) {
                    const double2 wd = *(const double2*)(wr + 4 * m);
                    const ull wx = __double_as_longlong(wd.x);
                    const ull wy = __double_as_longlong(wd.y);
                    acc[2 * m]         = fma2(xa, wx, acc[2 * m]);
                    acc[2 * m + 1]     = fma2(xa, wy, acc[2 * m + 1]);
                    acc[8 + 2 * m]     = fma2(xb, wx, acc[8 + 2 * m]);
                    acc[8 + 2 * m + 1] = fma2(xb, wy, acc[8 + 2 * m + 1]);
                }
            }
            // 4. epilogue (primal lanes tanh; tangent lanes g*dz via shfl)
            const int psrc = lane & ~1;
            const bool prim = (lane & 1) == 0;
#pragma unroll
            for (int j = 0; j < 8; j += 2) {
                const float z0a = sum2(acc[j]),     z0b = sum2(acc[j + 1]);
                const float z1a = sum2(acc[8 + j]), z1b = sum2(acc[8 + j + 1]);
                float h0a = 0.f, h0b = 0.f, h1a = 0.f, h1b = 0.f;
                float g0a = 0.f, g0b = 0.f, g1a = 0.f, g1b = 0.f;
                if (prim) {
                    const float ba = smf[MB2 + warp * 8 + j];
                    const float bb = smf[MB2 + warp * 8 + j + 1];
                    h0a = tanh_fast(z0a + ba); g0a = 1.f - h0a * h0a;
                    h0b = tanh_fast(z0b + bb); g0b = 1.f - h0b * h0b;
                    h1a = tanh_fast(z1a + ba); g1a = 1.f - h1a * h1a;
                    h1b = tanh_fast(z1b + bb); g1b = 1.f - h1b * h1b;
                }
                const float s0a = __shfl_sync(FULL, g0a, psrc);
                const float s0b = __shfl_sync(FULL, g0b, psrc);
                const float s1a = __shfl_sync(FULL, g1a, psrc);
                const float s1b = __shfl_sync(FULL, g1b, psrc);
                const float v0a = prim ? h0a : s0a * z0a;
                const float v0b = prim ? h0b : s0b * z0b;
                const float v1a = prim ? h1a : s1a * z1a;
                const float v1b = prim ? h1b : s1b * z1b;
                *(ull*)&smf[MH2 + lane * 130 + warp * 8 + j] = packf2(v0a, v0b);
                *(ull*)&smf[MH2 + (lane + 32) * 130 + warp * 8 + j] = packf2(v1a, v1b);
            }
        }
        __syncthreads();

        // 5. fwd L3: warps 0..13 -> t-pair
        if (warp < 14) {
            const int t0 = warp * 2;
            ull a4[4] = {0ull, 0ull, 0ull, 0ull};
            const float* x0 = &smf[MH2 + lane * 130];
            const float* x1 = &smf[MH2 + (lane + 32) * 130];
            const float* wb = &smf[W3P + warp * 4];
#pragma unroll 2
            for (int kp = 0; kp < 64; kp++) {
                const ull xa = *(const ull*)(x0 + 2 * kp);
                const ull xb = *(const ull*)(x1 + 2 * kp);
                const double2 wd = *(const double2*)(wb + kp * 56);
                const ull wx = __double_as_longlong(wd.x);
                const ull wy = __double_as_longlong(wd.y);
                a4[0] = fma2(xa, wx, a4[0]);
                a4[1] = fma2(xa, wy, a4[1]);
                a4[2] = fma2(xb, wx, a4[2]);
                a4[3] = fma2(xb, wy, a4[3]);
            }
            const bool prim = (lane & 1) == 0;
            const float bb0 = prim ? smf[MB3 + t0] : 0.f;
            const float bb1 = prim ? smf[MB3 + t0 + 1] : 0.f;
            smf[MA3 + lane * 30 + t0]            = sum2(a4[0]) + bb0;
            smf[MA3 + lane * 30 + t0 + 1]        = sum2(a4[1]) + bb1;
            smf[MA3 + (lane + 32) * 30 + t0]     = sum2(a4[2]) + bb0;
            smf[MA3 + (lane + 32) * 30 + t0 + 1] = sum2(a4[3]) + bb1;
        }
        __syncthreads();

        // 6. mini-assembly: L, sig, u0, tauA, cotangent ghat
#pragma unroll 1
        for (int rr = 0; rr < 2; rr++) {
            const int e = rr * 16 + warp;
            if (b0 + e < batch) {
                float dqv = 0.f, ddqv = 0.f;
                if (lane < 7) {
                    dqv = smf[MXIN + e * 24 + 8 + lane];
                    ddqv = smf[MXIN + e * 24 + 16 + lane];
                }
                const float* ap = &smf[MA3 + (2 * e) * 30];
                const float* at = &smf[MA3 + (2 * e + 1) * 30];
                float Lm[28], Db[28], sig[7];
#pragma unroll
                for (int t = 0; t < 28; t++) { Lm[t] = ap[t]; Db[t] = at[t]; }
#pragma unroll
                for (int r = 0; r < 7; r++) {
                    const int td = TRI(r, r);
                    const float p = Lm[td];
                    sig[r] = sigmf(p);
                    Lm[td] = softplusf(p);
                    Db[td] *= sig[r];
                }
                float dqs[7], dds[7];
#pragma unroll
                for (int r = 0; r < 7; r++) {
                    dqs[r] = __shfl_sync(FULL, dqv, r);
                    dds[r] = __shfl_sync(FULL, ddqv, r);
                }
                float u0[7], t2[7], wv[7];
#pragma unroll
                for (int c = 0; c < 7; c++) {
                    float s = 0.f, s2 = 0.f, s3 = 0.f;
#pragma unroll
                    for (int r = 0; r < 7; r++) {
                        if (r >= c) {
                            const int t = TRI(r, c);
                            s = fmaf(Lm[t], dqs[r], s);
                            s2 = fmaf(Lm[t], dds[r], s2);
                            s3 = fmaf(Db[t], dqs[r], s3);
                        }
                    }
                    u0[c] = s; t2[c] = s2; wv[c] = s3;
                }
                float tsel = 0.f;
#pragma unroll
                for (int i = 0; i < 7; i++) {
                    float s = 0.f;
#pragma unroll
                    for (int c = 0; c <= i; c++) {
                        s = fmaf(Lm[TRI(i, c)], t2[c] + wv[c], s);
                        s = fmaf(Db[TRI(i, c)], u0[c], s);
                    }
                    if (lane == i) tsel = s;
                }
                if (lane < 7) smf[MTA + e * 8 + lane] = tsel;
                if (lane < 28) {
                    const float sq = sqrtf((float)(8 * lane + 1));
                    const int r = (int)((sq - 1.f) * 0.5f);
                    const int c = lane - r * (r + 1) / 2;
                    float g = dqs[r] * u0[c];
                    if (r == c) g *= sig[r];
                    smf[MGH + e * 30 + lane] = g;
                }
            }
        }
        __syncthreads();

        // 7. bwd L3 (splat form): warp->i-pairs warp*4..+3, lane=element
        {
            ull acc[4] = {0ull, 0ull, 0ull, 0ull};
            const float* gh = &smf[MGH + lane * 30];
#pragma unroll
            for (int t = 0; t < 28; t++) {
                const float gv = gh[t];
                const ull gs = packf2(gv, gv);
#pragma unroll
                for (int m = 0; m < 4; m++)
                    acc[m] = fma2(gs, *(const ull*)&smf[W3P + (warp * 4 + m) * 56 + 2 * t], acc[m]);
            }
#pragma unroll
            for (int m = 0; m < 4; m++) {
                float ba, bb; unpk2(acc[m], ba, bb);
                const int i0 = warp * 8 + 2 * m;
                const float h0 = smf[MH2 + (2 * lane) * 130 + i0];
                const float h1 = smf[MH2 + (2 * lane) * 130 + i0 + 1];
                *(ull*)&smf[BZ2 + lane * 130 + i0] =
                    packf2((1.f - h0 * h0) * ba, (1.f - h1 * h1) * bb);
            }
        }
        __syncthreads();

        // 8. bwd L2 (splat form): warp->k-pairs warp*4..+3, lane=element
        {
            ull acc[4] = {0ull, 0ull, 0ull, 0ull};
            const float* bz = &smf[BZ2 + lane * 130];
#pragma unroll 4
            for (int i = 0; i < 128; i++) {
                const float bv = bz[i];
                const ull s = packf2(bv, bv);
#pragma unroll
                for (int m = 0; m < 4; m++)
                    acc[m] = fma2(s, *(const ull*)&smf[W2P + (warp * 4 + m) * 256 + 2 * i], acc[m]);
            }
#pragma unroll
            for (int m = 0; m < 4; m++) {
                float ba, bb; unpk2(acc[m], ba, bb);
                const int k0 = warp * 8 + 2 * m;
                const float h0 = smf[MH1 + (2 * lane) * 130 + k0];
                const float h1 = smf[MH1 + (2 * lane) * 130 + k0 + 1];
                *(ull*)&smf[BZ1 + lane * 130 + k0] =
                    packf2((1.f - h0 * h0) * ba, (1.f - h1 * h1) * bb);
            }
        }
        __syncthreads();

        // 9. bwd L1 + output: m_j = W1 bz1; tau = tauA - m
#pragma unroll 1
        for (int rr = 0; rr < 2; rr++) {
            const int e = rr * 16 + warp;
            const int b = b0 + e;
            if (b < batch) {
                float mj[7] = {0.f, 0.f, 0.f, 0.f, 0.f, 0.f, 0.f};
#pragma unroll
                for (int m4 = 0; m4 < 4; m4++) {
                    const int k = m4 * 32 + lane;
                    const float bv = smf[BZ1 + e * 130 + k];
#pragma unroll
                    for (int j = 0; j < 7; j++) mj[j] = fmaf(smf[MW1 + j * 128 + k], bv, mj[j]);
                }
#pragma unroll
                for (int j = 0; j < 7; j++) {
                    mj[j] += __shfl_xor_sync(FULL, mj[j], 16);
                    mj[j] += __shfl_xor_sync(FULL, mj[j], 8);
                    mj[j] += __shfl_xor_sync(FULL, mj[j], 4);
                    mj[j] += __shfl_xor_sync(FULL, mj[j], 2);
                    mj[j] += __shfl_xor_sync(FULL, mj[j], 1);
                }
                float sel = 0.f;
#pragma unroll
                for (int j = 0; j < 7; j++) if (lane == j) sel = mj[j];
                if (lane < 7) out[b * 7 + lane] = smf[MTA + e * 8 + lane] - sel;
            }
        }
        __syncthreads();
    }
}

// =====================================================================
// Kernel 2: damping + potential (R7 version, passing).
// =====================================================================
#define DW1   0
#define DB1   1792
#define DW2P  1920
#define DB2   18304
#define DW3P  18432
#define DB3   22016
#define DPT   22048
#define DSP2  23072
#define DH1   23200
#define DH2   39840
#define D_TOT 56480
#define DA3   DH1
#define DXIN  DH2

__global__ __launch_bounds__(512, 1) void k_damp(
    const float* __restrict__ q, const float* __restrict__ dq,
    const float* __restrict__ dW1, const float* __restrict__ db1,
    const float* __restrict__ dW2, const float* __restrict__ db2,
    const float* __restrict__ dW3, const float* __restrict__ db3,
    const float* __restrict__ pW1, const float* __restrict__ pb1,
    const float* __restrict__ pw2,
    float* __restrict__ out, int batch)
{
    extern __shared__ float sm[];
    const int tid = threadIdx.x;
    for (int i = tid; i < 1792; i += 512) sm[DW1 + i] = dW1[i];
    for (int i = tid; i < 128; i += 512) {
        sm[DB1 + i] = db1[i]; sm[DB2 + i] = db2[i]; sm[DSP2 + i] = softplusf(pw2[i]);
    }
    for (int idx = tid; idx < 16384; idx += 512) {
        const int kp = idx >> 8, r = idx & 255;
        sm[DW2P + idx] = dW2[(2 * kp + (r & 1)) * 128 + (r >> 1)];
    }
    for (int idx = tid; idx < 3584; idx += 512) {
        const int kp = idx / 56, r = idx % 56;
        sm[DW3P + idx] = dW3[(2 * kp + (r & 1)) * 28 + (r >> 1)];
    }
    for (int idx = tid; idx < 1024; idx += 512) {
        const int h = idx >> 3, j = idx & 7;
        sm[DPT + idx] = (j < 7) ? pW1[j * 128 + h] : pb1[h];
    }
    for (int i = tid; i < 32; i += 512) sm[DB3 + i] = (i < 28) ? db3[i] : 0.f;
    __syncthreads();

    const int lane = tid & 31;
    const int warp = tid >> 5;
    const int o    = warp & 7;
    const int rh   = warp >> 3;
    const int R0   = rh * 64 + lane;
    const int R1   = R0 + 32;

    const int i1 = tid & 127;
    const int eg = tid >> 7;
    float w1r[14];
#pragma unroll
    for (int d = 0; d < 14; d++) w1r[d] = sm[DW1 + d * 128 + i1];
    const float b1r = sm[DB1 + i1];

    const int ntiles = (batch + 127) >> 7;
    for (int tile = blockIdx.x; tile < ntiles; tile += gridDim.x) {
        const int b0 = tile << 7;

        for (int idx = tid; idx < 1792; idx += 512) {
            const int e = idx / 14, d = idx % 14;
            const int b = b0 + e;
            float v = 0.f;
            if (b < batch) v = (d < 7) ? q[b * 7 + d] : dq[b * 7 + d - 7];
            sm[DXIN + idx] = v;
        }
        __syncthreads();

#pragma unroll 2
        for (int it = 0; it < 32; it++) {
            const int e = eg * 32 + it;
            const float* xe = &sm[DXIN + e * 14];
            float z = b1r;
#pragma unroll
            for (int d = 0; d < 14; d++) z = fmaf(xe[d], w1r[d], z);
            sm[DH1 + e * 130 + i1] = tanh_fast(z);
        }
        __syncthreads();

        {
            ull acc0[16], acc1[16];
#pragma unroll
            for (int ii = 0; ii < 16; ii++) { acc0[ii] = 0ull; acc1[ii] = 0ull; }
            const float* x0 = &sm[DH1 + R0 * 130];
            const float* x1 = &sm[DH1 + R1 * 130];
            const float* wb = &sm[DW2P + o * 32];
#pragma unroll 1
            for (int kp = 0; kp < 64; kp++) {
                const ull xa = *(const ull*)(x0 + 2 * kp);
                const ull xb = *(const ull*)(x1 + 2 * kp);
                const float* wr = wb + kp * 256;
#pragma unroll
                for (int m = 0; m < 8; m++) {
                    const double2 wd = *(const double2*)(wr + 4 * m);
                    const ull wx = __double_as_longlong(wd.x);
                    const ull wy = __double_as_longlong(wd.y);
                    acc0[2 * m]     = fma2(xa, wx, acc0[2 * m]);
                    acc1[2 * m]     = fma2(xb, wx, acc1[2 * m]);
                    acc0[2 * m + 1] = fma2(xa, wy, acc0[2 * m + 1]);
                    acc1[2 * m + 1] = fma2(xb, wy, acc1[2 * m + 1]);
                }
            }
            float* y0 = &sm[DH2 + R0 * 130 + o * 16];
            float* y1 = &sm[DH2 + R1 * 130 + o * 16];
#pragma unroll
            for (int m = 0; m < 8; m++) {
                const float ba = sm[DB2 + o * 16 + 2 * m];
                const float bb = sm[DB2 + o * 16 + 2 * m + 1];
                const float v0a = tanh_fast(sum2(acc0[2 * m]) + ba);
                const float v0b = tanh_fast(sum2(acc0[2 * m + 1]) + bb);
                const float v1a = tanh_fast(sum2(acc1[2 * m]) + ba);
                const float v1b = tanh_fast(sum2(acc1[2 * m + 1]) + bb);
                *(ull*)(y0 + 2 * m) = packf2(v0a, v0b);
                *(ull*)(y1 + 2 * m) = packf2(v1a, v1b);
            }
        }
        __syncthreads();

        if (o < 7) {
            ull a0[4] = {0,0,0,0}, a1[4] = {0,0,0,0};
            const float* x0 = &sm[DH2 + R0 * 130];
            const float* x1 = &sm[DH2 + R1 * 130];
#pragma unroll 1
            for (int kp = 0; kp < 64; kp++) {
                const ull xa = *(const ull*)(x0 + 2 * kp);
                const ull xb = *(const ull*)(x1 + 2 * kp);
                const float* wr = &sm[DW3P + kp * 56 + o * 8];
                const double2 w0 = *(const double2*)(wr);
                const double2 w1 = *(const double2*)(wr + 4);
                const ull wA = __double_as_longlong(w0.x), wB = __double_as_longlong(w0.y);
                const ull wC = __double_as_longlong(w1.x), wD = __double_as_longlong(w1.y);
                a0[0] = fma2(xa, wA, a0[0]); a1[0] = fma2(xb, wA, a1[0]);
                a0[1] = fma2(xa, wB, a0[1]); a1[1] = fma2(xb, wB, a1[1]);
                a0[2] = fma2(xa, wC, a0[2]); a1[2] = fma2(xb, wC, a1[2]);
                a0[3] = fma2(xa, wD, a0[3]); a1[3] = fma2(xb, wD, a1[3]);
            }
#pragma unroll
            for (int j = 0; j < 4; j++) {
                const int i = o * 4 + j;
                const float bb = sm[DB3 + i];
                sm[DA3 + R0 * 33 + i] = sum2(a0[j]) + bb;
                sm[DA3 + R1 * 33 + i] = sum2(a1[j]) + bb;
            }
        }
        __syncthreads();

#pragma unroll 1
        for (int rr = 0; rr < 8; rr++) {
            const int e = rr * 16 + warp;
            const int b = b0 + e;
            if (b < batch) {
                float qv = 0.f, dqv = 0.f;
                if (lane < 7) { qv = q[b * 7 + lane]; dqv = dq[b * 7 + lane]; }
                float qs[7], dqs[7];
#pragma unroll
                for (int r = 0; r < 7; r++) {
                    qs[r] = __shfl_sync(FULL, qv, r);
                    dqs[r] = __shfl_sync(FULL, dqv, r);
                }
                float gp[7] = {0.f,0.f,0.f,0.f,0.f,0.f,0.f};
#pragma unroll
                for (int hh = 0; hh < 4; hh++) {
                    const int h = hh * 32 + lane;
                    const float4 r0 = *(const float4*)&sm[DPT + h * 8];
                    const float4 r1 = *(const float4*)&sm[DPT + h * 8 + 4];
                    float z = r1.w;
                    z = fmaf(qs[0], r0.x, z); z = fmaf(qs[1], r0.y, z);
                    z = fmaf(qs[2], r0.z, z); z = fmaf(qs[3], r0.w, z);
                    z = fmaf(qs[4], r1.x, z); z = fmaf(qs[5], r1.y, z);
                    z = fmaf(qs[6], r1.z, z);
                    const float s = sigmf(z) * sm[DSP2 + h];
                    gp[0] = fmaf(r0.x, s, gp[0]); gp[1] = fmaf(r0.y, s, gp[1]);
                    gp[2] = fmaf(r0.z, s, gp[2]); gp[3] = fmaf(r0.w, s, gp[3]);
                    gp[4] = fmaf(r1.x, s, gp[4]); gp[5] = fmaf(r1.y, s, gp[5]);
                    gp[6] = fmaf(r1.z, s, gp[6]);
                }
#pragma unroll
                for (int j = 0; j < 7; j++) {
                    gp[j] += __shfl_xor_sync(FULL, gp[j], 16);
                    gp[j] += __shfl_xor_sync(FULL, gp[j], 8);
                    gp[j] += __shfl_xor_sync(FULL, gp[j], 4);
                    gp[j] += __shfl_xor_sync(FULL, gp[j], 2);
                    gp[j] += __shfl_xor_sync(FULL, gp[j], 1);
                }
                const float* scr = &sm[DA3 + e * 33];
                float Lm[28];
#pragma unroll
                for (int t = 0; t < 28; t++) Lm[t] = scr[t];
#pragma unroll
                for (int r = 0; r < 7; r++) Lm[TRI(r, r)] = softplusf(Lm[TRI(r, r)]);
                float u[7];
#pragma unroll
                for (int c = 0; c < 7; c++) {
                    float s = 0.f;
#pragma unroll
                    for (int r = 0; r < 7; r++)
                        if (r >= c) s = fmaf(Lm[TRI(r, c)], dqs[r], s);
                    u[c] = s;
                }
                float outsel = 0.f;
#pragma unroll
                for (int i = 0; i < 7; i++) {
                    float s = gp[i];
#pragma unroll
                    for (int c = 0; c <= i; c++) s = fmaf(Lm[TRI(i, c)], u[c], s);
                    if (lane == i) outsel = s;
                }
                if (lane < 7) out[b * 7 + lane] += outsel;
            }
        }
        __syncthreads();
    }
}

// =====================================================================
extern "C" void kernel_launch(void* const* d_in, const int* in_sizes, int n_in,
                              void* d_out, int out_size)
{
    const float* q   = (const float*)d_in[0];
    const float* dq  = (const float*)d_in[1];
    const float* ddq = (const float*)d_in[2];
    const float* mW1 = (const float*)d_in[3];
    const float* mb1 = (const float*)d_in[4];
    const float* mW2 = (const float*)d_in[5];
    const float* mb2 = (const float*)d_in[6];
    const float* mW3 = (const float*)d_in[7];
    const float* mb3 = (const float*)d_in[8];
    const float* dW1 = (const float*)d_in[9];
    const float* db1 = (const float*)d_in[10];
    const float* dW2 = (const float*)d_in[11];
    const float* db2 = (const float*)d_in[12];
    const float* dW3 = (const float*)d_in[13];
    const float* db3 = (const float*)d_in[14];
    const float* pW1 = (const float*)d_in[15];
    const float* pb1 = (const float*)d_in[16];
    const float* pw2 = (const float*)d_in[17];
    float* out = (float*)d_out;

    const int batch = in_sizes[0] / 7;

    const size_t sm1 = (size_t)M_TOT * sizeof(float);
    const size_t sm2 = (size_t)D_TOT * sizeof(float);

    cudaFuncSetAttribute(k_mass, cudaFuncAttributeMaxDynamicSharedMemorySize, (int)sm1);
    cudaFuncSetAttribute(k_damp, cudaFuncAttributeMaxDynamicSharedMemorySize, (int)sm2);

    k_mass<<<148, 512, sm1>>>(q, dq, ddq, mW1, mb1, mW2, mb2, mW3, mb3, out, batch);
    k_damp<<<148, 512, sm2>>>(q, dq, dW1, db1, dW2, db2, dW3, db3, pW1, pb1, pw2, out, batch);
}

// round 11
// speedup vs baseline: 2.0065x; 1.0067x over previous
#include <cuda_runtime.h>
#include <math.h>

#define FULL 0xffffffffu
typedef unsigned long long ull;
typedef unsigned int u32;

static __device__ __forceinline__ float softplusf(float x) {
    return fmaxf(x, 0.f) + log1pf(expf(-fabsf(x)));
}
static __device__ __forceinline__ float sigmf(float x) {
    return __fdividef(1.f, 1.f + __expf(-x));
}
static __device__ __forceinline__ float tanh_fast(float x) {
    const float e = __expf(2.f * x);
    return 1.f - __fdividef(2.f, e + 1.f);
}
__host__ __device__ constexpr int TRI(int r, int c) { return r * (r + 1) / 2 + c; }

static __device__ __forceinline__ ull fma2(ull a, ull b, ull c) {
    ull d;
    asm("fma.rn.f32x2 %0, %1, %2, %3;" : "=l"(d) : "l"(a), "l"(b), "l"(c));
    return d;
}
static __device__ __forceinline__ float sum2(ull v) {
    u32 l, h;
    asm("mov.b64 {%0, %1}, %2;" : "=r"(l), "=r"(h) : "l"(v));
    return __uint_as_float(l) + __uint_as_float(h);
}
static __device__ __forceinline__ void unpk2(ull v, float& a, float& b) {
    u32 l, h;
    asm("mov.b64 {%0, %1}, %2;" : "=r"(l), "=r"(h) : "l"(v));
    a = __uint_as_float(l); b = __uint_as_float(h);
}
static __device__ __forceinline__ ull packf2(float lo, float hi) {
    ull d;
    asm("mov.b64 %0, {%1, %2};" : "=l"(d) : "r"(__float_as_uint(lo)), "r"(__float_as_uint(hi)));
    return d;
}

__device__ __constant__ int TRIR[28] = {0,1,1,2,2,2,3,3,3,3,4,4,4,4,4,5,5,5,5,5,5,6,6,6,6,6,6,6};
__device__ __constant__ int TRIC[28] = {0,0,1,0,1,2,0,1,2,3,0,1,2,3,4,0,1,2,3,4,5,0,1,2,3,4,5,6};

// =====================================================================
// k_mass: JVP+VJP + gradV. Tile = 32 elements, 64 fwd rows.
// 512 thr, 16 warps.
// =====================================================================
#define MW1   0        // [7][128]
#define MB1   896
#define MB2   1024
#define MB3   1152
#define PW    1184     // pW1 [7][128]
#define PB    2080
#define SP2   2208
#define W2P   2336     // [kp64][2i+p] -> 18720
#define W3P   18720    // [ip64][2t+p] -> 22304
#define MXIN  22304    // [32][24] -> 23072
#define MH1   23072    // [64][130] -> 31392
#define MH2   31392    // [64][130] -> 39712
#define MA3   39712    // [64][30] -> 41632
#define MGH   41632    // [32][29] -> 42560
#define MTA   42560    // [32][8]  -> 42816
#define BZ2   42816    // [32][130] -> 46976
#define BZ1   46976    // [32][130] -> 51136
#define M_TOT 51136

__global__ __launch_bounds__(512, 1) void k_mass(
    const float* __restrict__ q, const float* __restrict__ dq, const float* __restrict__ ddq,
    const float* __restrict__ mW1, const float* __restrict__ mb1,
    const float* __restrict__ mW2, const float* __restrict__ mb2,
    const float* __restrict__ mW3, const float* __restrict__ mb3,
    const float* __restrict__ pW1, const float* __restrict__ pb1,
    const float* __restrict__ pw2,
    float* __restrict__ out, int batch)
{
    extern __shared__ float smf[];
    const int tid = threadIdx.x;
    const int lane = tid & 31;
    const int warp = tid >> 5;

    for (int i = tid; i < 896; i += 512) { smf[MW1 + i] = mW1[i]; smf[PW + i] = pW1[i]; }
    for (int i = tid; i < 128; i += 512) {
        smf[MB1 + i] = mb1[i]; smf[MB2 + i] = mb2[i];
        smf[PB + i] = pb1[i]; smf[SP2 + i] = softplusf(pw2[i]);
    }
    for (int i = tid; i < 32; i += 512) smf[MB3 + i] = (i < 28) ? mb3[i] : 0.f;
    for (int idx = tid; idx < 16384; idx += 512) {
        const int kp = idx >> 8, r = idx & 255;
        smf[W2P + idx] = mW2[(2 * kp + (r & 1)) * 128 + (r >> 1)];
    }
    for (int idx = tid; idx < 3584; idx += 512) {
        const int kp = idx / 56, r = idx % 56;
        smf[W3P + idx] = mW3[(2 * kp + (r & 1)) * 28 + (r >> 1)];
    }
    __syncthreads();

    const int i1 = tid & 127;
    const int eg = tid >> 7;
    float w1r[7];
#pragma unroll
    for (int d = 0; d < 7; d++) w1r[d] = smf[MW1 + d * 128 + i1];
    const float b1r = smf[MB1 + i1];

    const int ntiles = (batch + 31) >> 5;
    for (int tile = blockIdx.x; tile < ntiles; tile += gridDim.x) {
        const int b0 = tile << 5;

        // 1. stage XIN
        for (int idx = tid; idx < 768; idx += 512) {
            const int e = idx / 24, s = idx % 24;
            const int b = b0 + e;
            float v = 0.f;
            if (b < batch) {
                if (s < 7) v = q[b * 7 + s];
                else if (s >= 8 && s < 15) v = dq[b * 7 + s - 8];
                else if (s >= 16 && s < 23) v = ddq[b * 7 + s - 16];
            }
            smf[MXIN + idx] = v;
        }
        __syncthreads();

        // 2. layer1 primal + tangent
#pragma unroll
        for (int it = 0; it < 8; it++) {
            const int e = eg * 8 + it;
            const float* xe = &smf[MXIN + e * 24];
            float z = b1r, dz = 0.f;
#pragma unroll
            for (int d = 0; d < 7; d++) {
                z = fmaf(xe[d], w1r[d], z);
                dz = fmaf(xe[8 + d], w1r[d], dz);
            }
            const float h = tanh_fast(z);
            smf[MH1 + (2 * e) * 130 + i1] = h;
            smf[MH1 + (2 * e + 1) * 130 + i1] = (1.f - h * h) * dz;
        }
        __syncthreads();

        // 3. fwd L2
        {
            ull acc[16];
#pragma unroll
            for (int m = 0; m < 16; m++) acc[m] = 0ull;
            const float* x0 = &smf[MH1 + lane * 130];
            const float* x1 = &smf[MH1 + (lane + 32) * 130];
            const float* wb = &smf[W2P + warp * 16];
#pragma unroll 2
            for (int kp = 0; kp < 64; kp++) {
                const ull xa = *(const ull*)(x0 + 2 * kp);
                const ull xb = *(const ull*)(x1 + 2 * kp);
                const float* wr = wb + kp * 256;
#pragma unroll
                for (int m = 0; m < 4; m++) {
                    const double2 wd = *(const double2*)(wr + 4 * m);
                    const ull wx = __double_as_longlong(wd.x);
                    const ull wy = __double_as_longlong(wd.y);
                    acc[2 * m]         = fma2(xa, wx, acc[2 * m]);
                    acc[2 * m + 1]     = fma2(xa, wy, acc[2 * m + 1]);
                    acc[8 + 2 * m]     = fma2(xb, wx, acc[8 + 2 * m]);
                    acc[8 + 2 * m + 1] = fma2(xb, wy, acc[8 + 2 * m + 1]);
                }
            }
            // 4. epilogue
            const int psrc = lane & ~1;
            const bool prim = (lane & 1) == 0;
#pragma unroll
            for (int j = 0; j < 8; j += 2) {
                const float z0a = sum2(acc[j]),     z0b = sum2(acc[j + 1]);
                const float z1a = sum2(acc[8 + j]), z1b = sum2(acc[8 + j + 1]);
                float h0a = 0.f, h0b = 0.f, h1a = 0.f, h1b = 0.f;
                float g0a = 0.f, g0b = 0.f, g1a = 0.f, g1b = 0.f;
                if (prim) {
                    const float ba = smf[MB2 + warp * 8 + j];
                    const float bb = smf[MB2 + warp * 8 + j + 1];
                    h0a = tanh_fast(z0a + ba); g0a = 1.f - h0a * h0a;
                    h0b = tanh_fast(z0b + bb); g0b = 1.f - h0b * h0b;
                    h1a = tanh_fast(z1a + ba); g1a = 1.f - h1a * h1a;
                    h1b = tanh_fast(z1b + bb); g1b = 1.f - h1b * h1b;
                }
                const float s0a = __shfl_sync(FULL, g0a, psrc);
                const float s0b = __shfl_sync(FULL, g0b, psrc);
                const float s1a = __shfl_sync(FULL, g1a, psrc);
                const float s1b = __shfl_sync(FULL, g1b, psrc);
                const float v0a = prim ? h0a : s0a * z0a;
                const float v0b = prim ? h0b : s0b * z0b;
                const float v1a = prim ? h1a : s1a * z1a;
                const float v1b = prim ? h1b : s1b * z1b;
                *(ull*)&smf[MH2 + lane * 130 + warp * 8 + j] = packf2(v0a, v0b);
                *(ull*)&smf[MH2 + (lane + 32) * 130 + warp * 8 + j] = packf2(v1a, v1b);
            }
        }
        __syncthreads();

        // 5. fwd L3
        if (warp < 14) {
            const int t0 = warp * 2;
            ull a4[4] = {0ull, 0ull, 0ull, 0ull};
            const float* x0 = &smf[MH2 + lane * 130];
            const float* x1 = &smf[MH2 + (lane + 32) * 130];
            const float* wb = &smf[W3P + warp * 4];
#pragma unroll 2
            for (int kp = 0; kp < 64; kp++) {
                const ull xa = *(const ull*)(x0 + 2 * kp);
                const ull xb = *(const ull*)(x1 + 2 * kp);
                const double2 wd = *(const double2*)(wb + kp * 56);
                const ull wx = __double_as_longlong(wd.x);
                const ull wy = __double_as_longlong(wd.y);
                a4[0] = fma2(xa, wx, a4[0]);
                a4[1] = fma2(xa, wy, a4[1]);
                a4[2] = fma2(xb, wx, a4[2]);
                a4[3] = fma2(xb, wy, a4[3]);
            }
            const bool prim = (lane & 1) == 0;
            const float bb0 = prim ? smf[MB3 + t0] : 0.f;
            const float bb1 = prim ? smf[MB3 + t0 + 1] : 0.f;
            smf[MA3 + lane * 30 + t0]            = sum2(a4[0]) + bb0;
            smf[MA3 + lane * 30 + t0 + 1]        = sum2(a4[1]) + bb1;
            smf[MA3 + (lane + 32) * 30 + t0]     = sum2(a4[2]) + bb0;
            smf[MA3 + (lane + 32) * 30 + t0 + 1] = sum2(a4[3]) + bb1;
        }
        __syncthreads();

        // 6. mini-assembly: L, sig, u0, tauA, cotangent ghat
#pragma unroll 1
        for (int rr = 0; rr < 2; rr++) {
            const int e = rr * 16 + warp;
            if (b0 + e < batch) {
                float dqv = 0.f, ddqv = 0.f;
                if (lane < 7) {
                    dqv = smf[MXIN + e * 24 + 8 + lane];
                    ddqv = smf[MXIN + e * 24 + 16 + lane];
                }
                const float* ap = &smf[MA3 + (2 * e) * 30];
                const float* at = &smf[MA3 + (2 * e + 1) * 30];
                float Lm[28], Db[28], sig[7];
#pragma unroll
                for (int t = 0; t < 28; t++) { Lm[t] = ap[t]; Db[t] = at[t]; }
#pragma unroll
                for (int r = 0; r < 7; r++) {
                    const int td = TRI(r, r);
                    const float p = Lm[td];
                    sig[r] = sigmf(p);
                    Lm[td] = softplusf(p);
                    Db[td] *= sig[r];
                }
                float dqs[7], dds[7];
#pragma unroll
                for (int r = 0; r < 7; r++) {
                    dqs[r] = __shfl_sync(FULL, dqv, r);
                    dds[r] = __shfl_sync(FULL, ddqv, r);
                }
                float u0[7], t2[7], wv[7];
#pragma unroll
                for (int c = 0; c < 7; c++) {
                    float s = 0.f, s2 = 0.f, s3 = 0.f;
#pragma unroll
                    for (int r = 0; r < 7; r++) {
                        if (r >= c) {
                            const int t = TRI(r, c);
                            s = fmaf(Lm[t], dqs[r], s);
                            s2 = fmaf(Lm[t], dds[r], s2);
                            s3 = fmaf(Db[t], dqs[r], s3);
                        }
                    }
                    u0[c] = s; t2[c] = s2; wv[c] = s3;
                }
                float tsel = 0.f;
#pragma unroll
                for (int i = 0; i < 7; i++) {
                    float s = 0.f;
#pragma unroll
                    for (int c = 0; c <= i; c++) {
                        s = fmaf(Lm[TRI(i, c)], t2[c] + wv[c], s);
                        s = fmaf(Db[TRI(i, c)], u0[c], s);
                    }
                    if (lane == i) tsel = s;
                }
                if (lane < 7) smf[MTA + e * 8 + lane] = tsel;
                if (lane < 28) {
                    const int r = TRIR[lane], c = TRIC[lane];
                    float g = dqs[r] * u0[c];
                    if (r == c) g *= sig[r];
                    smf[MGH + e * 29 + lane] = g;
                }
            }
        }
        __syncthreads();

        // 7. bwd L3 (splat): warp->i-pairs, lane=element
        {
            ull acc[4] = {0ull, 0ull, 0ull, 0ull};
            const float* gh = &smf[MGH + lane * 29];
#pragma unroll
            for (int t = 0; t < 28; t++) {
                const float gv = gh[t];
                const ull gs = packf2(gv, gv);
#pragma unroll
                for (int m = 0; m < 4; m++)
                    acc[m] = fma2(gs, *(const ull*)&smf[W3P + (warp * 4 + m) * 56 + 2 * t], acc[m]);
            }
#pragma unroll
            for (int m = 0; m < 4; m++) {
                float ba, bb; unpk2(acc[m], ba, bb);
                const int i0 = warp * 8 + 2 * m;
                float h0, h1;
                unpk2(*(const ull*)&smf[MH2 + (2 * lane) * 130 + i0], h0, h1);
                *(ull*)&smf[BZ2 + lane * 130 + i0] =
                    packf2((1.f - h0 * h0) * ba, (1.f - h1 * h1) * bb);
            }
        }
        __syncthreads();

        // 8. bwd L2 (splat): warp->k-pairs, lane=element
        {
            ull acc[4] = {0ull, 0ull, 0ull, 0ull};
            const float* bz = &smf[BZ2 + lane * 130];
#pragma unroll 4
            for (int i = 0; i < 128; i++) {
                const float bv = bz[i];
                const ull s = packf2(bv, bv);
#pragma unroll
                for (int m = 0; m < 4; m++)
                    acc[m] = fma2(s, *(const ull*)&smf[W2P + (warp * 4 + m) * 256 + 2 * i], acc[m]);
            }
#pragma unroll
            for (int m = 0; m < 4; m++) {
                float ba, bb; unpk2(acc[m], ba, bb);
                const int k0 = warp * 8 + 2 * m;
                float h0, h1;
                unpk2(*(const ull*)&smf[MH1 + (2 * lane) * 130 + k0], h0, h1);
                *(ull*)&smf[BZ1 + lane * 130 + k0] =
                    packf2((1.f - h0 * h0) * ba, (1.f - h1 * h1) * bb);
            }
        }
        __syncthreads();

        // 9. bwd L1 + gradV + output: acc7 = gv - m; tau = tauA + sel
#pragma unroll 1
        for (int rr = 0; rr < 2; rr++) {
            const int e = rr * 16 + warp;
            const int b = b0 + e;
            if (b < batch) {
                float qv = 0.f;
                if (lane < 7) qv = smf[MXIN + e * 24 + lane];
                float qs[7];
#pragma unroll
                for (int r = 0; r < 7; r++) qs[r] = __shfl_sync(FULL, qv, r);
                float acc7[7] = {0.f, 0.f, 0.f, 0.f, 0.f, 0.f, 0.f};
                // bwd L1 (negative sign folded in)
#pragma unroll
                for (int m4 = 0; m4 < 4; m4++) {
                    const int k = m4 * 32 + lane;
                    const float bv = smf[BZ1 + e * 130 + k];
#pragma unroll
                    for (int j = 0; j < 7; j++) acc7[j] = fmaf(-smf[MW1 + j * 128 + k], bv, acc7[j]);
                }
                // gradV
#pragma unroll
                for (int hh = 0; hh < 4; hh++) {
                    const int h = hh * 32 + lane;
                    float wv[7];
                    float z = smf[PB + h];
#pragma unroll
                    for (int d = 0; d < 7; d++) {
                        wv[d] = smf[PW + d * 128 + h];
                        z = fmaf(qs[d], wv[d], z);
                    }
                    const float s = sigmf(z) * smf[SP2 + h];
#pragma unroll
                    for (int d = 0; d < 7; d++) acc7[d] = fmaf(wv[d], s, acc7[d]);
                }
#pragma unroll
                for (int j = 0; j < 7; j++) {
                    acc7[j] += __shfl_xor_sync(FULL, acc7[j], 16);
                    acc7[j] += __shfl_xor_sync(FULL, acc7[j], 8);
                    acc7[j] += __shfl_xor_sync(FULL, acc7[j], 4);
                    acc7[j] += __shfl_xor_sync(FULL, acc7[j], 2);
                    acc7[j] += __shfl_xor_sync(FULL, acc7[j], 1);
                }
                float sel = 0.f;
#pragma unroll
                for (int j = 0; j < 7; j++) if (lane == j) sel = acc7[j];
                if (lane < 7) out[b * 7 + lane] = smf[MTA + e * 8 + lane] + sel;
            }
        }
        __syncthreads();
    }
}

// =====================================================================
// Kernel 2: damping only (gradV moved to k_mass). 512 thr.
// =====================================================================
#define DW1   0
#define DB1   1792
#define DW2P  1920
#define DB2   18304
#define DW3P  18432
#define DB3   22016
#define DH1   23200
#define DH2   39840
#define D_TOT 56480
#define DA3   DH1
#define DXIN  DH2

__global__ __launch_bounds__(512, 1) void k_damp(
    const float* __restrict__ q, const float* __restrict__ dq,
    const float* __restrict__ dW1, const float* __restrict__ db1,
    const float* __restrict__ dW2, const float* __restrict__ db2,
    const float* __restrict__ dW3, const float* __restrict__ db3,
    float* __restrict__ out, int batch)
{
    extern __shared__ float sm[];
    const int tid = threadIdx.x;
    for (int i = tid; i < 1792; i += 512) sm[DW1 + i] = dW1[i];
    for (int i = tid; i < 128; i += 512) { sm[DB1 + i] = db1[i]; sm[DB2 + i] = db2[i]; }
    for (int idx = tid; idx < 16384; idx += 512) {
        const int kp = idx >> 8, r = idx & 255;
        sm[DW2P + idx] = dW2[(2 * kp + (r & 1)) * 128 + (r >> 1)];
    }
    for (int idx = tid; idx < 3584; idx += 512) {
        const int kp = idx / 56, r = idx % 56;
        sm[DW3P + idx] = dW3[(2 * kp + (r & 1)) * 28 + (r >> 1)];
    }
    for (int i = tid; i < 32; i += 512) sm[DB3 + i] = (i < 28) ? db3[i] : 0.f;
    __syncthreads();

    const int lane = tid & 31;
    const int warp = tid >> 5;
    const int o    = warp & 7;
    const int rh   = warp >> 3;
    const int R0   = rh * 64 + lane;
    const int R1   = R0 + 32;

    const int i1 = tid & 127;
    const int eg = tid >> 7;
    float w1r[14];
#pragma unroll
    for (int d = 0; d < 14; d++) w1r[d] = sm[DW1 + d * 128 + i1];
    const float b1r = sm[DB1 + i1];

    const int ntiles = (batch + 127) >> 7;
    for (int tile = blockIdx.x; tile < ntiles; tile += gridDim.x) {
        const int b0 = tile << 7;

        for (int idx = tid; idx < 1792; idx += 512) {
            const int e = idx / 14, d = idx % 14;
            const int b = b0 + e;
            float v = 0.f;
            if (b < batch) v = (d < 7) ? q[b * 7 + d] : dq[b * 7 + d - 7];
            sm[DXIN + idx] = v;
        }
        __syncthreads();

#pragma unroll 2
        for (int it = 0; it < 32; it++) {
            const int e = eg * 32 + it;
            const float* xe = &sm[DXIN + e * 14];
            float z = b1r;
#pragma unroll
            for (int d = 0; d < 14; d++) z = fmaf(xe[d], w1r[d], z);
            sm[DH1 + e * 130 + i1] = tanh_fast(z);
        }
        __syncthreads();

        {
            ull acc0[16], acc1[16];
#pragma unroll
            for (int ii = 0; ii < 16; ii++) { acc0[ii] = 0ull; acc1[ii] = 0ull; }
            const float* x0 = &sm[DH1 + R0 * 130];
            const float* x1 = &sm[DH1 + R1 * 130];
            const float* wb = &sm[DW2P + o * 32];
#pragma unroll 1
            for (int kp = 0; kp < 64; kp++) {
                const ull xa = *(const ull*)(x0 + 2 * kp);
                const ull xb = *(const ull*)(x1 + 2 * kp);
                const float* wr = wb + kp * 256;
#pragma unroll
                for (int m = 0; m < 8; m++) {
                    const double2 wd = *(const double2*)(wr + 4 * m);
                    const ull wx = __double_as_longlong(wd.x);
                    const ull wy = __double_as_longlong(wd.y);
                    acc0[2 * m]     = fma2(xa, wx, acc0[2 * m]);
                    acc1[2 * m]     = fma2(xb, wx, acc1[2 * m]);
                    acc0[2 * m + 1] = fma2(xa, wy, acc0[2 * m + 1]);
                    acc1[2 * m + 1] = fma2(xb, wy, acc1[2 * m + 1]);
                }
            }
            float* y0 = &sm[DH2 + R0 * 130 + o * 16];
            float* y1 = &sm[DH2 + R1 * 130 + o * 16];
#pragma unroll
            for (int m = 0; m < 8; m++) {
                const float ba = sm[DB2 + o * 16 + 2 * m];
                const float bb = sm[DB2 + o * 16 + 2 * m + 1];
                const float v0a = tanh_fast(sum2(acc0[2 * m]) + ba);
                const float v0b = tanh_fast(sum2(acc0[2 * m + 1]) + bb);
                const float v1a = tanh_fast(sum2(acc1[2 * m]) + ba);
                const float v1b = tanh_fast(sum2(acc1[2 * m + 1]) + bb);
                *(ull*)(y0 + 2 * m) = packf2(v0a, v0b);
                *(ull*)(y1 + 2 * m) = packf2(v1a, v1b);
            }
        }
        __syncthreads();

        if (o < 7) {
            ull a0[4] = {0,0,0,0}, a1[4] = {0,0,0,0};
            const float* x0 = &sm[DH2 + R0 * 130];
            const float* x1 = &sm[DH2 + R1 * 130];
#pragma unroll 1
            for (int kp = 0; kp < 64; kp++) {
                const ull xa = *(const ull*)(x0 + 2 * kp);
                const ull xb = *(const ull*)(x1 + 2 * kp);
                const float* wr = &sm[DW3P + kp * 56 + o * 8];
                const double2 w0 = *(const double2*)(wr);
                const double2 w1 = *(const double2*)(wr + 4);
                const ull wA = __double_as_longlong(w0.x), wB = __double_as_longlong(w0.y);
                const ull wC = __double_as_longlong(w1.x), wD = __double_as_longlong(w1.y);
                a0[0] = fma2(xa, wA, a0[0]); a1[0] = fma2(xb, wA, a1[0]);
                a0[1] = fma2(xa, wB, a0[1]); a1[1] = fma2(xb, wB, a1[1]);
                a0[2] = fma2(xa, wC, a0[2]); a1[2] = fma2(xb, wC, a1[2]);
                a0[3] = fma2(xa, wD, a0[3]); a1[3] = fma2(xb, wD, a1[3]);
            }
#pragma unroll
            for (int j = 0; j < 4; j++) {
                const int i = o * 4 + j;
                const float bb = sm[DB3 + i];
                sm[DA3 + R0 * 33 + i] = sum2(a0[j]) + bb;
                sm[DA3 + R1 * 33 + i] = sum2(a1[j]) + bb;
            }
        }
        __syncthreads();

#pragma unroll 1
        for (int rr = 0; rr < 8; rr++) {
            const int e = rr * 16 + warp;
            const int b = b0 + e;
            if (b < batch) {
                float dqv = 0.f;
                if (lane < 7) dqv = dq[b * 7 + lane];
                float dqs[7];
#pragma unroll
                for (int r = 0; r < 7; r++) dqs[r] = __shfl_sync(FULL, dqv, r);
                const float* scr = &sm[DA3 + e * 33];
                float Lm[28];
#pragma unroll
                for (int t = 0; t < 28; t++) Lm[t] = scr[t];
#pragma unroll
                for (int r = 0; r < 7; r++) Lm[TRI(r, r)] = softplusf(Lm[TRI(r, r)]);
                float u[7];
#pragma unroll
                for (int c = 0; c < 7; c++) {
                    float s = 0.f;
#pragma unroll
                    for (int r = 0; r < 7; r++)
                        if (r >= c) s = fmaf(Lm[TRI(r, c)], dqs[r], s);
                    u[c] = s;
                }
                float outsel = 0.f;
#pragma unroll
                for (int i = 0; i < 7; i++) {
                    float s = 0.f;
#pragma unroll
                    for (int c = 0; c <= i; c++) s = fmaf(Lm[TRI(i, c)], u[c], s);
                    if (lane == i) outsel = s;
                }
                if (lane < 7) out[b * 7 + lane] += outsel;
            }
        }
        __syncthreads();
    }
}

// =====================================================================
extern "C" void kernel_launch(void* const* d_in, const int* in_sizes, int n_in,
                              void* d_out, int out_size)
{
    const float* q   = (const float*)d_in[0];
    const float* dq  = (const float*)d_in[1];
    const float* ddq = (const float*)d_in[2];
    const float* mW1 = (const float*)d_in[3];
    const float* mb1 = (const float*)d_in[4];
    const float* mW2 = (const float*)d_in[5];
    const float* mb2 = (const float*)d_in[6];
    const float* mW3 = (const float*)d_in[7];
    const float* mb3 = (const float*)d_in[8];
    const float* dW1 = (const float*)d_in[9];
    const float* db1 = (const float*)d_in[10];
    const float* dW2 = (const float*)d_in[11];
    const float* db2 = (const float*)d_in[12];
    const float* dW3 = (const float*)d_in[13];
    const float* db3 = (const float*)d_in[14];
    const float* pW1 = (const float*)d_in[15];
    const float* pb1 = (const float*)d_in[16];
    const float* pw2 = (const float*)d_in[17];
    float* out = (float*)d_out;

    const int batch = in_sizes[0] / 7;

    const size_t sm1 = (size_t)M_TOT * sizeof(float);
    const size_t sm2 = (size_t)D_TOT * sizeof(float);

    cudaFuncSetAttribute(k_mass, cudaFuncAttributeMaxDynamicSharedMemorySize, (int)sm1);
    cudaFuncSetAttribute(k_damp, cudaFuncAttributeMaxDynamicSharedMemorySize, (int)sm2);

    k_mass<<<148, 512, sm1>>>(q, dq, ddq, mW1, mb1, mW2, mb2, mW3, mb3,
                              pW1, pb1, pw2, out, batch);
    k_damp<<<148, 512, sm2>>>(q, dq, dW1, db1, dW2, db2, dW3, db3, out, batch);
}